// round 15
// baseline (speedup 1.0000x reference)
#include <cuda_runtime.h>
#include <cstdint>

// ---------------- scratch (device globals; no allocation APIs) ----------------
__device__ float    g_h   [32768u*256u];     // fp32 hidden (residual), 32MB
__device__ float    g_colsum[512];

// bf16x2 packed (hi,lo) operand arrays; u32 = {odd<<16 | even}
__device__ uint32_t g_zh   [32u*1024u*256u];
__device__ uint32_t g_qkvh [32768u*384u], g_qkvl [32768u*384u];
__device__ uint32_t g_hh   [32768u*128u], g_hl   [32768u*128u];
__device__ uint32_t g_attnh[32768u*128u], g_attnl[32768u*128u];
__device__ uint32_t g_ffh  [32768u*512u], g_ffl  [32768u*512u];
__device__ uint32_t g_wrh  [256u*256u],   g_wrl  [256u*256u];
__device__ uint32_t g_wqh  [2u*768u*128u],g_wql  [2u*768u*128u];
__device__ uint32_t g_woh  [2u*256u*128u],g_wol  [2u*256u*128u];
__device__ uint32_t g_w1h  [2u*1024u*128u],g_w1l [2u*1024u*128u];
__device__ uint32_t g_w2h  [2u*256u*512u],g_w2l  [2u*256u*512u];

// ---------------- bf16 split helpers ----------------
__device__ __forceinline__ void split2(float e, float o, uint32_t& hi, uint32_t& lo) {
    asm("cvt.rn.bf16x2.f32 %0, %1, %2;" : "=r"(hi) : "f"(o), "f"(e));
    float he = __uint_as_float(hi << 16);
    float ho = __uint_as_float(hi & 0xffff0000u);
    asm("cvt.rn.bf16x2.f32 %0, %1, %2;" : "=r"(lo) : "f"(o - ho), "f"(e - he));
}

__device__ __forceinline__ uint32_t prmt(uint32_t a, uint32_t b, uint32_t s) {
    uint32_t r;
    asm("prmt.b32 %0, %1, %2, %3;" : "=r"(r) : "r"(a), "r"(b), "r"(s));
    return r;
}

// ---------------- fused weight split ----------------
__global__ void wsplit_all_kernel(
    const float* __restrict__ Wread, const float* __restrict__ Wqkv,
    const float* __restrict__ Wo,    const float* __restrict__ W1,
    const float* __restrict__ W2,
    uint32_t* __restrict__ wrh, uint32_t* __restrict__ wrl,
    uint32_t* __restrict__ wqh, uint32_t* __restrict__ wql,
    uint32_t* __restrict__ woh, uint32_t* __restrict__ wol,
    uint32_t* __restrict__ w1h, uint32_t* __restrict__ w1l,
    uint32_t* __restrict__ w2h, uint32_t* __restrict__ w2l)
{
    int i = blockIdx.x * 256 + threadIdx.x;
    const float* src; uint32_t *H, *L; int off;
    if (i < 65536)        { src = Wread; H = wrh; L = wrl; off = i; }
    else if (i < 262144)  { src = Wqkv;  H = wqh; L = wql; off = i - 65536; }
    else if (i < 327680)  { src = Wo;    H = woh; L = wol; off = i - 262144; }
    else if (i < 589824)  { src = W1;    H = w1h; L = w1l; off = i - 327680; }
    else if (i < 851968)  { src = W2;    H = w2h; L = w2l; off = i - 589824; }
    else return;
    float2 v = *(const float2*)(src + 2 * off);
    split2(v.x, v.y, H[off], L[off]);
}

// ---------------- column sums of Wres ----------------
__global__ void colsum_kernel(const float* __restrict__ Wres) {
    int r = threadIdx.x;
    float s0 = 0.f, s1 = 0.f, s2 = 0.f, s3 = 0.f;
    #pragma unroll 4
    for (int rr = 0; rr < 512; rr += 4) {
        s0 += Wres[(rr + 0) * 512 + r];
        s1 += Wres[(rr + 1) * 512 + r];
        s2 += Wres[(rr + 2) * 512 + r];
        s3 += Wres[(rr + 3) * 512 + r];
    }
    g_colsum[r] = (s0 + s1) + (s2 + s3);
}

// ---------------- LIF reservoir (R9 verbatim) ----------------
__global__ void __launch_bounds__(512) lif_kernel(
    const float* __restrict__ x, const float* __restrict__ Win,
    const float* __restrict__ Wres, uint32_t* __restrict__ zh)
{
    const int b = blockIdx.x;
    const int r = threadIdx.x;
    const int warp = r >> 5, lane = r & 31;

    __shared__ float sWin[8][512];
    __shared__ int   s_act[512];
    __shared__ int   s_in[512];
    __shared__ int   s_wcnt[16];

    #pragma unroll
    for (int i = 0; i < 8; i++) sWin[i][r] = Win[i * 512 + r];

    const float colsum = g_colsum[r];
    const float* xb = x + (size_t)b * 1024 * 8;
    uint32_t* zb = zh + (size_t)b * 1024 * 256;

    float v = 0.f, isyn = 0.f;
    int zprev = 0;

    for (int t = 0; t < 1024; t++) {
        const int na = __syncthreads_count(zprev);

        float rec;
        if (na == 512) {
            rec = colsum;
        } else if (na == 0) {
            rec = 0.f;
        } else {
            unsigned bal = __ballot_sync(0xffffffffu, zprev);
            if (lane == 0) s_wcnt[warp] = __popc(bal);
            __syncthreads();
            int base_a = 0;
            #pragma unroll
            for (int w = 0; w < 16; w++) {
                int c = s_wcnt[w];
                if (w < warp) base_a += c;
            }
            int rank = __popc(bal & ((1u << lane) - 1u));
            if (zprev) s_act[base_a + rank] = r;
            else       s_in[warp * 32 - base_a + (lane - rank)] = r;
            __syncthreads();

            if (na <= 256) {
                rec = 0.f;
                for (int j = 0; j < na; j++) rec += Wres[s_act[j] * 512 + r];
            } else {
                const int ni = 512 - na;
                float a0 = 0.f, a1 = 0.f, a2 = 0.f, a3 = 0.f;
                int j = 0;
                for (; j + 4 <= ni; j += 4) {
                    a0 += Wres[s_in[j + 0] * 512 + r];
                    a1 += Wres[s_in[j + 1] * 512 + r];
                    a2 += Wres[s_in[j + 2] * 512 + r];
                    a3 += Wres[s_in[j + 3] * 512 + r];
                }
                for (; j < ni; j++) a0 += Wres[s_in[j] * 512 + r];
                rec = colsum - ((a0 + a1) + (a2 + a3));
            }
        }

        float cur = 0.f;
        #pragma unroll
        for (int i = 0; i < 8; i++) cur += xb[t * 8 + i] * sWin[i][r];

        float total = cur + rec;
        float vdec = v + 0.004f * (isyn - v);
        float idec = isyn * 0.8f;
        int z = (vdec - 0.1f) > 0.f ? 1 : 0;
        v = z ? 0.f : vdec;
        isyn = idec + total;

        int zn = __shfl_down_sync(0xffffffffu, z, 1);
        if (!(r & 1))
            zb[t * 256 + (r >> 1)] = (z ? 0x3f80u : 0u) | (zn ? 0x3f800000u : 0u);
        zprev = z;
    }
}

// ---------------- MMA helpers ----------------
__device__ __forceinline__ void mma_bf16(float* c, const uint32_t* a, const uint32_t* b) {
    asm volatile(
        "mma.sync.aligned.m16n8k16.row.col.f32.bf16.bf16.f32 "
        "{%0,%1,%2,%3},{%4,%5,%6,%7},{%8,%9},{%0,%1,%2,%3};\n"
        : "+f"(c[0]), "+f"(c[1]), "+f"(c[2]), "+f"(c[3])
        : "r"(a[0]), "r"(a[1]), "r"(a[2]), "r"(a[3]), "r"(b[0]), "r"(b[1]));
}

__device__ __forceinline__ void cp_async16(uint32_t saddr, const void* gptr) {
    asm volatile("cp.async.ca.shared.global [%0], [%1], 16;\n" :: "r"(saddr), "l"(gptr));
}

__device__ __forceinline__ void ldsm_x4(uint32_t& r0, uint32_t& r1,
                                        uint32_t& r2, uint32_t& r3, uint32_t saddr) {
    asm volatile("ldmatrix.sync.aligned.m8n8.x4.shared.b16 {%0,%1,%2,%3}, [%4];"
        : "=r"(r0), "=r"(r1), "=r"(r2), "=r"(r3) : "r"(saddr));
}

// ---------------- bf16x3 tensor-core GEMM (R12 verbatim) ----------------
#define PA 20
#define MAT_U32 (128 * PA)
#define STAGE_U32 (4 * MAT_U32)
#define GEMM_SMEM_BYTES (2 * STAGE_U32 * 4)

__global__ void __launch_bounds__(256, 2) gemm_bf16x3(
    const uint32_t* __restrict__ Ah, const uint32_t* __restrict__ Al,
    const uint32_t* __restrict__ Bh, const uint32_t* __restrict__ Bl,
    const float* __restrict__ bias, const float* __restrict__ Radd,
    float* __restrict__ C, uint32_t* __restrict__ Ch, uint32_t* __restrict__ Cl,
    int M, int N, int K, int relu)
{
    extern __shared__ uint32_t smem_u[];
    const int KP   = K >> 1;
    const int tid  = threadIdx.x;
    const int lane = tid & 31;
    const int warp = tid >> 5;
    const int bm   = blockIdx.y << 7;
    const int bn   = blockIdx.x << 7;
    const int warpM = (warp >> 1) << 5;
    const int warpN = (warp & 1) << 6;
    const int g = lane >> 2;
    const int t = lane & 3;
    const bool hasAl = (Al != nullptr);

    const uint32_t sbase = (uint32_t)__cvta_generic_to_shared(smem_u);

    const int lm = lane >> 3, lr = lane & 7;
    const uint32_t aRow = (uint32_t)(warpM + ((lm & 1) << 3) + lr);
    const uint32_t aCol = (uint32_t)((lm >> 1) << 2);
    const uint32_t bRow = (uint32_t)(warpN + ((lm >> 1) << 3) + lr);
    const uint32_t bCol = (uint32_t)((lm & 1) << 2);

    float acc[2][8][4];
    #pragma unroll
    for (int mi = 0; mi < 2; mi++)
        #pragma unroll
        for (int ni = 0; ni < 8; ni++)
            #pragma unroll
            for (int r = 0; r < 4; r++) acc[mi][ni][r] = 0.f;

    const int ntiles = K >> 5;

    auto issue = [&](int kt, int s) {
        uint32_t st = sbase + (uint32_t)(s * STAGE_U32) * 4u;
        #pragma unroll
        for (int i = 0; i < 2; i++) {
            int slot = tid + (i << 8);
            int row = slot >> 2, c4 = (slot & 3) << 2;
            size_t go = (size_t)row * KP + kt * 16 + c4;
            uint32_t so = (uint32_t)(row * PA + c4) * 4u;
            cp_async16(st + 0 * MAT_U32 * 4u + so, Ah + (size_t)bm * KP + go);
            if (hasAl)
                cp_async16(st + 1 * MAT_U32 * 4u + so, Al + (size_t)bm * KP + go);
            cp_async16(st + 2 * MAT_U32 * 4u + so, Bh + (size_t)bn * KP + go);
            cp_async16(st + 3 * MAT_U32 * 4u + so, Bl + (size_t)bn * KP + go);
        }
        asm volatile("cp.async.commit_group;\n");
    };

    issue(0, 0);
    if (ntiles > 1) issue(1, 1);

    for (int kt = 0; kt < ntiles; kt++) {
        const int s = kt & 1;
        if (kt + 2 < ntiles)
            asm volatile("cp.async.wait_group 1;\n" ::: "memory");
        else
            asm volatile("cp.async.wait_group 0;\n" ::: "memory");
        __syncthreads();

        const uint32_t stage = sbase + (uint32_t)(s * STAGE_U32) * 4u;
        const uint32_t aBaseH = stage + (aRow * PA + aCol) * 4u;
        const uint32_t bBaseH = stage + 2u * MAT_U32 * 4u + (bRow * PA + bCol) * 4u;

        #pragma unroll
        for (int ch = 0; ch < 2; ch++) {
            const uint32_t cc = (uint32_t)(ch << 3) * 4u;

            uint32_t ah[2][4], alr[2][4];
            #pragma unroll
            for (int mi = 0; mi < 2; mi++) {
                const uint32_t aa = aBaseH + (uint32_t)(mi * 16 * PA) * 4u + cc;
                ldsm_x4(ah[mi][0], ah[mi][1], ah[mi][2], ah[mi][3], aa);
                if (hasAl)
                    ldsm_x4(alr[mi][0], alr[mi][1], alr[mi][2], alr[mi][3],
                            aa + (uint32_t)MAT_U32 * 4u);
            }

            #pragma unroll
            for (int p = 0; p < 4; p++) {
                const uint32_t ba = bBaseH + (uint32_t)(p * 16 * PA) * 4u + cc;
                uint32_t b0h[2], b1h[2], b0l[2], b1l[2];
                ldsm_x4(b0h[0], b0h[1], b1h[0], b1h[1], ba);
                ldsm_x4(b0l[0], b0l[1], b1l[0], b1l[1], ba + (uint32_t)MAT_U32 * 4u);

                const int n0 = 2 * p, n1 = 2 * p + 1;
                mma_bf16(acc[0][n0], ah[0], b0h);
                mma_bf16(acc[0][n0], ah[0], b0l);
                mma_bf16(acc[1][n0], ah[1], b0h);
                mma_bf16(acc[1][n0], ah[1], b0l);
                mma_bf16(acc[0][n1], ah[0], b1h);
                mma_bf16(acc[0][n1], ah[0], b1l);
                mma_bf16(acc[1][n1], ah[1], b1h);
                mma_bf16(acc[1][n1], ah[1], b1l);
                if (hasAl) {
                    mma_bf16(acc[0][n0], alr[0], b0h);
                    mma_bf16(acc[1][n0], alr[1], b0h);
                    mma_bf16(acc[0][n1], alr[0], b1h);
                    mma_bf16(acc[1][n1], alr[1], b1h);
                }
            }
        }

        __syncthreads();
        if (kt + 2 < ntiles) issue(kt + 2, s);
    }

    const int cq = t << 1;
    #pragma unroll
    for (int ni = 0; ni < 8; ni++) {
        const int col = bn + warpN + (ni << 3) + cq;
        const float b0 = bias[col], b1 = bias[col + 1];
        #pragma unroll
        for (int mi = 0; mi < 2; mi++) {
            const int row0 = bm + warpM + (mi << 4) + g;
            float2 v0, v1;
            v0.x = acc[mi][ni][0] + b0; v0.y = acc[mi][ni][1] + b1;
            v1.x = acc[mi][ni][2] + b0; v1.y = acc[mi][ni][3] + b1;
            if (Radd) {
                float2 r0 = *(const float2*)&Radd[(size_t)row0 * N + col];
                float2 r1 = *(const float2*)&Radd[(size_t)(row0 + 8) * N + col];
                v0.x += r0.x; v0.y += r0.y;
                v1.x += r1.x; v1.y += r1.y;
            }
            if (relu) {
                v0.x = fmaxf(v0.x, 0.f); v0.y = fmaxf(v0.y, 0.f);
                v1.x = fmaxf(v1.x, 0.f); v1.y = fmaxf(v1.y, 0.f);
            }
            if (C) {
                *(float2*)&C[(size_t)row0 * N + col] = v0;
                *(float2*)&C[(size_t)(row0 + 8) * N + col] = v1;
            }
            if (Ch) {
                const int NP = N >> 1;
                const int pc = col >> 1;
                uint32_t ph, pl;
                split2(v0.x, v0.y, ph, pl);
                Ch[(size_t)row0 * NP + pc] = ph;
                Cl[(size_t)row0 * NP + pc] = pl;
                split2(v1.x, v1.y, ph, pl);
                Ch[(size_t)(row0 + 8) * NP + pc] = ph;
                Cl[(size_t)(row0 + 8) * NP + pc] = pl;
            }
        }
    }
}

// ---------------- bf16x3 GEMM + residual + LayerNorm fused (N = 256) ----------
// Block tile 64x256: 8 warps as 2x4 (warp tile 32x64). Each CTA owns full rows
// -> LN in epilogue. A,B pre-split pairs (always 3-term). Writes LN output fp32
// + optional bf16 pairs. Stage u32 layout: Ah 0, Al 1280, Bh 2560, Bl 7680.
#define LNG_STAGE_U32 12800
#define LNG_SMEM_BYTES (2 * LNG_STAGE_U32 * 4)   // 102400

__global__ void __launch_bounds__(256, 2) gemm_ln_bf16x3(
    const uint32_t* __restrict__ Ah, const uint32_t* __restrict__ Al,
    const uint32_t* __restrict__ Bh, const uint32_t* __restrict__ Bl,
    const float* __restrict__ bias, const float* __restrict__ Radd,
    const float* __restrict__ lng, const float* __restrict__ lnb,
    float* __restrict__ Cout, uint32_t* __restrict__ Ch, uint32_t* __restrict__ Cl,
    int K)
{
    extern __shared__ uint32_t S[];
    const int KP   = K >> 1;
    const int tid  = threadIdx.x;
    const int lane = tid & 31;
    const int warp = tid >> 5;
    const int bm   = blockIdx.x << 6;        // 64 rows per CTA
    const int warpM = (warp >> 2) << 5;      // 0,32
    const int warpN = (warp & 3) << 6;       // 0,64,128,192
    const int g = lane >> 2;
    const int t = lane & 3;

    const uint32_t sbase = (uint32_t)__cvta_generic_to_shared(S);

    const int lm = lane >> 3, lr = lane & 7;
    const uint32_t aRow = (uint32_t)(warpM + ((lm & 1) << 3) + lr);    // 0..63
    const uint32_t aCol = (uint32_t)((lm >> 1) << 2);
    const uint32_t bRow = (uint32_t)(warpN + ((lm >> 1) << 3) + lr);   // 0..255
    const uint32_t bCol = (uint32_t)((lm & 1) << 2);

    float acc[2][8][4];
    #pragma unroll
    for (int mi = 0; mi < 2; mi++)
        #pragma unroll
        for (int ni = 0; ni < 8; ni++)
            #pragma unroll
            for (int r = 0; r < 4; r++) acc[mi][ni][r] = 0.f;

    const int ntiles = K >> 5;

    auto issue = [&](int kt, int s) {
        uint32_t st = sbase + (uint32_t)(s * LNG_STAGE_U32) * 4u;
        {   // A: 256 slots, 1/thread per mat
            int row = tid >> 2, c4 = (tid & 3) << 2;
            size_t go = (size_t)row * KP + kt * 16 + c4;
            uint32_t so = (uint32_t)(row * PA + c4) * 4u;
            cp_async16(st + so,              Ah + (size_t)bm * KP + go);
            cp_async16(st + 1280u * 4u + so, Al + (size_t)bm * KP + go);
        }
        #pragma unroll
        for (int i = 0; i < 4; i++) {   // B: 1024 slots, 4/thread per mat
            int slot = i * 256 + tid;
            int row = slot >> 2, c4 = (slot & 3) << 2;
            size_t go = (size_t)row * KP + kt * 16 + c4;
            uint32_t so = (uint32_t)(row * PA + c4) * 4u;
            cp_async16(st + 2560u * 4u + so, Bh + go);
            cp_async16(st + 7680u * 4u + so, Bl + go);
        }
        asm volatile("cp.async.commit_group;\n");
    };

    issue(0, 0);
    if (ntiles > 1) issue(1, 1);

    for (int kt = 0; kt < ntiles; kt++) {
        const int s = kt & 1;
        if (kt + 2 < ntiles)
            asm volatile("cp.async.wait_group 1;\n" ::: "memory");
        else
            asm volatile("cp.async.wait_group 0;\n" ::: "memory");
        __syncthreads();

        const uint32_t stage = sbase + (uint32_t)(s * LNG_STAGE_U32) * 4u;
        const uint32_t aBaseH = stage + (aRow * PA + aCol) * 4u;
        const uint32_t bBaseH = stage + 2560u * 4u + (bRow * PA + bCol) * 4u;

        #pragma unroll
        for (int ch = 0; ch < 2; ch++) {
            const uint32_t cc = (uint32_t)(ch << 3) * 4u;

            uint32_t ah[2][4], alr[2][4];
            #pragma unroll
            for (int mi = 0; mi < 2; mi++) {
                const uint32_t aa = aBaseH + (uint32_t)(mi * 16 * PA) * 4u + cc;
                ldsm_x4(ah[mi][0], ah[mi][1], ah[mi][2], ah[mi][3], aa);
                ldsm_x4(alr[mi][0], alr[mi][1], alr[mi][2], alr[mi][3],
                        aa + 1280u * 4u);
            }

            #pragma unroll
            for (int p = 0; p < 4; p++) {
                const uint32_t ba = bBaseH + (uint32_t)(p * 16 * PA) * 4u + cc;
                uint32_t b0h[2], b1h[2], b0l[2], b1l[2];
                ldsm_x4(b0h[0], b0h[1], b1h[0], b1h[1], ba);
                ldsm_x4(b0l[0], b0l[1], b1l[0], b1l[1], ba + 5120u * 4u);

                const int n0 = 2 * p, n1 = 2 * p + 1;
                mma_bf16(acc[0][n0], ah[0], b0h);
                mma_bf16(acc[0][n0], ah[0], b0l);
                mma_bf16(acc[1][n0], ah[1], b0h);
                mma_bf16(acc[1][n0], ah[1], b0l);
                mma_bf16(acc[0][n1], ah[0], b1h);
                mma_bf16(acc[0][n1], ah[0], b1l);
                mma_bf16(acc[1][n1], ah[1], b1h);
                mma_bf16(acc[1][n1], ah[1], b1l);
                mma_bf16(acc[0][n0], alr[0], b0h);
                mma_bf16(acc[1][n0], alr[1], b0h);
                mma_bf16(acc[0][n1], alr[0], b1h);
                mma_bf16(acc[1][n1], alr[1], b1h);
            }
        }

        __syncthreads();
        if (kt + 2 < ntiles) issue(kt + 2, s);
    }
    // last loop iteration ended with __syncthreads(): SMEM reusable for LN.

    float* lns = (float*)S;   // [64 rows][4 warpN][2] floats = 2KB

    // v = acc + bias + residual; per-row partial sums
    #pragma unroll
    for (int mi = 0; mi < 2; mi++) {
        #pragma unroll
        for (int hf = 0; hf < 2; hf++) {
            const int r = warpM + mi * 16 + g + hf * 8;
            float s = 0.f, q = 0.f;
            #pragma unroll
            for (int ni = 0; ni < 8; ni++) {
                const int col = warpN + (ni << 3) + 2 * t;
                float2 rv = *(const float2*)&Radd[(size_t)(bm + r) * 256 + col];
                float v0 = acc[mi][ni][hf * 2]     + bias[col]     + rv.x;
                float v1 = acc[mi][ni][hf * 2 + 1] + bias[col + 1] + rv.y;
                acc[mi][ni][hf * 2]     = v0;
                acc[mi][ni][hf * 2 + 1] = v1;
                s += v0 + v1;
                q += v0 * v0 + v1 * v1;
            }
            s += __shfl_xor_sync(0xffffffffu, s, 1);
            q += __shfl_xor_sync(0xffffffffu, q, 1);
            s += __shfl_xor_sync(0xffffffffu, s, 2);
            q += __shfl_xor_sync(0xffffffffu, q, 2);
            if (t == 0) {
                lns[(r * 4 + (warpN >> 6)) * 2]     = s;
                lns[(r * 4 + (warpN >> 6)) * 2 + 1] = q;
            }
        }
    }
    __syncthreads();

    #pragma unroll
    for (int mi = 0; mi < 2; mi++) {
        #pragma unroll
        for (int hf = 0; hf < 2; hf++) {
            const int r = warpM + mi * 16 + g + hf * 8;
            float S4 = 0.f, Q4 = 0.f;
            #pragma unroll
            for (int wI = 0; wI < 4; wI++) {
                S4 += lns[(r * 4 + wI) * 2];
                Q4 += lns[(r * 4 + wI) * 2 + 1];
            }
            const float mean = S4 * (1.f / 256.f);
            const float var  = Q4 * (1.f / 256.f) - mean * mean;
            const float inv  = 1.f / sqrtf(var + 1e-5f);
            const size_t ro = (size_t)(bm + r) * 256;
            const size_t rp = (size_t)(bm + r) * 128;
            #pragma unroll
            for (int ni = 0; ni < 8; ni++) {
                const int col = warpN + (ni << 3) + 2 * t;
                float o0 = (acc[mi][ni][hf * 2]     - mean) * inv * lng[col]     + lnb[col];
                float o1 = (acc[mi][ni][hf * 2 + 1] - mean) * inv * lng[col + 1] + lnb[col + 1];
                *(float2*)&Cout[ro + col] = make_float2(o0, o1);
                if (Ch) {
                    uint32_t ph, pl;
                    split2(o0, o1, ph, pl);
                    Ch[rp + (col >> 1)] = ph;
                    Cl[rp + (col >> 1)] = pl;
                }
            }
        }
    }
}

// ---------------- bf16x3 MMA flash attention (R14 verbatim) --------------------
#define FLASH_SMEM_BYTES (18176 * 4)

__global__ void __launch_bounds__(256, 2) flash_mma_kernel(
    const uint32_t* __restrict__ qkvh, const uint32_t* __restrict__ qkvl,
    uint32_t* __restrict__ attnh, uint32_t* __restrict__ attnl)
{
    extern __shared__ uint32_t S[];
    uint32_t* KPh = S;
    uint32_t* KPl = S + 2304;
    uint32_t* VPh = S + 4608;
    uint32_t* VPl = S + 6784;
    uint32_t* Ph  = S + 8960;
    uint32_t* Pl  = S + 13568;

    const int tid  = threadIdx.x;
    const int lane = tid & 31;
    const int w    = tid >> 5;
    const int g    = lane >> 2;
    const int t    = lane & 3;
    const int qb   = blockIdx.x;
    const int bh   = blockIdx.y;
    const int b    = bh >> 2, h = bh & 3;

    const uint32_t sbase = (uint32_t)__cvta_generic_to_shared(S);
    const uint32_t* kph = qkvh + (size_t)b * 1024 * 384 + 128 + h * 32;
    const uint32_t* kpl = qkvl + (size_t)b * 1024 * 384 + 128 + h * 32;
    const uint32_t* vph = qkvh + (size_t)b * 1024 * 384 + 256 + h * 32;
    const uint32_t* vpl = qkvl + (size_t)b * 1024 * 384 + 256 + h * 32;

    const int wr = w * 16;
    const float SCALE = 0.125f;
    const float L2E   = 1.4426950408889634f;

    uint32_t qh[4][4], ql[4][4];
    {
        const size_t q0 = (size_t)(b * 1024 + qb * 128 + wr + g) * 384 + h * 32;
        const size_t q1 = q0 + (size_t)8 * 384;
        #pragma unroll
        for (int c = 0; c < 4; c++) {
            const int p = c * 8 + t;
            qh[c][0] = qkvh[q0 + p];     ql[c][0] = qkvl[q0 + p];
            qh[c][1] = qkvh[q1 + p];     ql[c][1] = qkvl[q1 + p];
            qh[c][2] = qkvh[q0 + p + 4]; ql[c][2] = qkvl[q0 + p + 4];
            qh[c][3] = qkvh[q1 + p + 4]; ql[c][3] = qkvl[q1 + p + 4];
        }
    }

    float oacc[8][4];
    #pragma unroll
    for (int nt = 0; nt < 8; nt++)
        #pragma unroll
        for (int r = 0; r < 4; r++) oacc[nt][r] = 0.f;
    float m0 = -1e30f, m1 = -1e30f, l0 = 0.f, l1 = 0.f;

    for (int kb = 0; kb < 16; kb++) {
        #pragma unroll
        for (int i = 0; i < 2; i++) {
            const int idx = i * 256 + tid;
            const int row = idx >> 3, q4 = (idx & 7) << 2;
            const size_t go = (size_t)(kb * 64 + row) * 384 + q4;
            const uint32_t so = (uint32_t)(row * 36 + q4) * 4u;
            cp_async16(sbase + so, kph + go);
            cp_async16(sbase + 2304u * 4u + so, kpl + go);
        }
        asm volatile("cp.async.commit_group;\n");

        {
            const int k2 = tid >> 3, j = tid & 7;
            const size_t r0 = (size_t)(kb * 64 + 2 * k2) * 384 + 4 * j;
            uint4 Ahv = *(const uint4*)&vph[r0];
            uint4 Bhv = *(const uint4*)&vph[r0 + 384];
            uint4 Alv = *(const uint4*)&vpl[r0];
            uint4 Blv = *(const uint4*)&vpl[r0 + 384];

            uint4 o0, o1;
            o0.x = prmt(Ahv.x, Bhv.x, 0x5410u); o0.y = prmt(Ahv.x, Bhv.x, 0x7632u);
            o0.z = prmt(Ahv.y, Bhv.y, 0x5410u); o0.w = prmt(Ahv.y, Bhv.y, 0x7632u);
            o1.x = prmt(Ahv.z, Bhv.z, 0x5410u); o1.y = prmt(Ahv.z, Bhv.z, 0x7632u);
            o1.z = prmt(Ahv.w, Bhv.w, 0x5410u); o1.w = prmt(Ahv.w, Bhv.w, 0x7632u);
            *(uint4*)&VPh[k2 * 68 + 8 * j]     = o0;
            *(uint4*)&VPh[k2 * 68 + 8 * j + 4] = o1;

            o0.x = prmt(Alv.x, Blv.x, 0x5410u); o0.y = prmt(Alv.x, Blv.x, 0x7632u);
            o0.z = prmt(Alv.y, Blv.y, 0x5410u); o0.w = prmt(Alv.y, Blv.y, 0x7632u);
            o1.x = prmt(Alv.z, Blv.z, 0x5410u); o1.y = prmt(Alv.z, Blv.z, 0x7632u);
            o1.z = prmt(Alv.w, Blv.w, 0x5410u); o1.w = prmt(Alv.w, Blv.w, 0x7632u);
            *(uint4*)&VPl[k2 * 68 + 8 * j]     = o0;
            *(uint4*)&VPl[k2 * 68 + 8 * j + 4] = o1;
        }
        asm volatile("cp.async.wait_group 0;\n" ::: "memory");
        __syncthreads();

        float sc[8][4];
        #pragma unroll
        for (int nt = 0; nt < 8; nt++)
            #pragma unroll
            for (int r = 0; r < 4; r++) sc[nt][r] = 0.f;

        #pragma unroll
        for (int c = 0; c < 4; c++) {
            const int c8 = c * 8 + t;
            #pragma unroll
            for (int nt = 0; nt < 8; nt++) {
                const uint32_t* kr = &KPh[(nt * 8 + g) * 36];
                const uint32_t* kl = &KPl[(nt * 8 + g) * 36];
                uint32_t bh2[2] = { kr[c8], kr[c8 + 4] };
                uint32_t bl2[2] = { kl[c8], kl[c8 + 4] };
                mma_bf16(sc[nt], qh[c], bh2);
                mma_bf16(sc[nt], qh[c], bl2);
                mma_bf16(sc[nt], ql[c], bh2);
            }
        }

        float mb0 = -1e30f, mb1 = -1e30f;
        #pragma unroll
        for (int nt = 0; nt < 8; nt++) {
            sc[nt][0] *= SCALE; sc[nt][1] *= SCALE;
            sc[nt][2] *= SCALE; sc[nt][3] *= SCALE;
            mb0 = fmaxf(mb0, fmaxf(sc[nt][0], sc[nt][1]));
            mb1 = fmaxf(mb1, fmaxf(sc[nt][2], sc[nt][3]));
        }
        #pragma unroll
        for (int off = 1; off <= 2; off <<= 1) {
            mb0 = fmaxf(mb0, __shfl_xor_sync(0xffffffffu, mb0, off));
            mb1 = fmaxf(mb1, __shfl_xor_sync(0xffffffffu, mb1, off));
        }
        const float mn0 = fmaxf(m0, mb0);
        const float mn1 = fmaxf(m1, mb1);
        const float c0 = exp2f((m0 - mn0) * L2E);
        const float c1 = exp2f((m1 - mn1) * L2E);
        l0 *= c0; l1 *= c1;
        #pragma unroll
        for (int nt = 0; nt < 8; nt++) {
            oacc[nt][0] *= c0; oacc[nt][1] *= c0;
            oacc[nt][2] *= c1; oacc[nt][3] *= c1;
        }
        #pragma unroll
        for (int nt = 0; nt < 8; nt++) {
            sc[nt][0] = exp2f((sc[nt][0] - mn0) * L2E);
            sc[nt][1] = exp2f((sc[nt][1] - mn0) * L2E);
            sc[nt][2] = exp2f((sc[nt][2] - mn1) * L2E);
            sc[nt][3] = exp2f((sc[nt][3] - mn1) * L2E);
            l0 += sc[nt][0] + sc[nt][1];
            l1 += sc[nt][2] + sc[nt][3];
        }
        m0 = mn0; m1 = mn1;

        #pragma unroll
        for (int nt = 0; nt < 8; nt++) {
            const int pc = nt * 4 + t;
            split2(sc[nt][0], sc[nt][1], Ph[(wr + g) * 36 + pc], Pl[(wr + g) * 36 + pc]);
            split2(sc[nt][2], sc[nt][3], Ph[(wr + g + 8) * 36 + pc], Pl[(wr + g + 8) * 36 + pc]);
        }
        __syncwarp();

        #pragma unroll
        for (int c = 0; c < 4; c++) {
            const int c8 = c * 8 + t;
            uint32_t ah2[4], al2[4];
            ah2[0] = Ph[(wr + g) * 36 + c8];
            ah2[1] = Ph[(wr + g + 8) * 36 + c8];
            ah2[2] = Ph[(wr + g) * 36 + c8 + 4];
            ah2[3] = Ph[(wr + g + 8) * 36 + c8 + 4];
            al2[0] = Pl[(wr + g) * 36 + c8];
            al2[1] = Pl[(wr + g + 8) * 36 + c8];
            al2[2] = Pl[(wr + g) * 36 + c8 + 4];
            al2[3] = Pl[(wr + g + 8) * 36 + c8 + 4];
            #pragma unroll
            for (int nt = 0; nt < 8; nt++) {
                const int vc = nt * 8 + g;
                uint32_t bh2[2] = { VPh[(c8) * 68 + vc], VPh[(c8 + 4) * 68 + vc] };
                uint32_t bl2[2] = { VPl[(c8) * 68 + vc], VPl[(c8 + 4) * 68 + vc] };
                mma_bf16(oacc[nt], ah2, bh2);
                mma_bf16(oacc[nt], ah2, bl2);
                mma_bf16(oacc[nt], al2, bh2);
            }
        }
        __syncthreads();
    }

    #pragma unroll
    for (int off = 1; off <= 2; off <<= 1) {
        l0 += __shfl_xor_sync(0xffffffffu, l0, off);
        l1 += __shfl_xor_sync(0xffffffffu, l1, off);
    }
    const float inv0 = 1.f / l0;
    const float inv1 = 1.f / l1;

    const int row0 = b * 1024 + qb * 128 + wr + g;
    #pragma unroll
    for (int nt = 0; nt < 8; nt++) {
        const int pc = h * 32 + (nt << 2) + t;
        uint32_t ph, pl;
        split2(oacc[nt][0] * inv0, oacc[nt][1] * inv0, ph, pl);
        attnh[(size_t)row0 * 128 + pc] = ph;
        attnl[(size_t)row0 * 128 + pc] = pl;
        split2(oacc[nt][2] * inv1, oacc[nt][3] * inv1, ph, pl);
        attnh[(size_t)(row0 + 8) * 128 + pc] = ph;
        attnl[(size_t)(row0 + 8) * 128 + pc] = pl;
    }
}

// -------------------------------- launch ---------------------------------------
extern "C" void kernel_launch(void* const* d_in, const int* in_sizes, int n_in,
                              void* d_out, int out_size)
{
    const float* x     = (const float*)d_in[0];
    const float* Win   = (const float*)d_in[1];
    const float* Wres  = (const float*)d_in[2];
    const float* Wread = (const float*)d_in[3];
    const float* bread = (const float*)d_in[4];
    const float* Wqkv  = (const float*)d_in[5];
    const float* bqkv  = (const float*)d_in[6];
    const float* Wo    = (const float*)d_in[7];
    const float* bo    = (const float*)d_in[8];
    const float* g1    = (const float*)d_in[9];
    const float* b1    = (const float*)d_in[10];
    const float* g2    = (const float*)d_in[11];
    const float* b2    = (const float*)d_in[12];
    const float* W1    = (const float*)d_in[13];
    const float* c1    = (const float*)d_in[14];
    const float* W2    = (const float*)d_in[15];
    const float* c2    = (const float*)d_in[16];
    float* out = (float*)d_out;

    float *h;
    uint32_t *zh, *qh, *ql_, *hh, *hl, *ath, *atl, *ffh, *ffl;
    uint32_t *wrh, *wrl, *wqh, *wql, *woh, *wol, *w1h, *w1l, *w2h, *w2l;
    cudaGetSymbolAddress((void**)&h,   g_h);
    cudaGetSymbolAddress((void**)&zh,  g_zh);
    cudaGetSymbolAddress((void**)&qh,  g_qkvh);
    cudaGetSymbolAddress((void**)&ql_, g_qkvl);
    cudaGetSymbolAddress((void**)&hh,  g_hh);
    cudaGetSymbolAddress((void**)&hl,  g_hl);
    cudaGetSymbolAddress((void**)&ath, g_attnh);
    cudaGetSymbolAddress((void**)&atl, g_attnl);
    cudaGetSymbolAddress((void**)&ffh, g_ffh);
    cudaGetSymbolAddress((void**)&ffl, g_ffl);
    cudaGetSymbolAddress((void**)&wrh, g_wrh);
    cudaGetSymbolAddress((void**)&wrl, g_wrl);
    cudaGetSymbolAddress((void**)&wqh, g_wqh);
    cudaGetSymbolAddress((void**)&wql, g_wql);
    cudaGetSymbolAddress((void**)&woh, g_woh);
    cudaGetSymbolAddress((void**)&wol, g_wol);
    cudaGetSymbolAddress((void**)&w1h, g_w1h);
    cudaGetSymbolAddress((void**)&w1l, g_w1l);
    cudaGetSymbolAddress((void**)&w2h, g_w2h);
    cudaGetSymbolAddress((void**)&w2l, g_w2l);

    cudaFuncSetAttribute(gemm_bf16x3,
                         cudaFuncAttributeMaxDynamicSharedMemorySize,
                         GEMM_SMEM_BYTES);
    cudaFuncSetAttribute(gemm_ln_bf16x3,
                         cudaFuncAttributeMaxDynamicSharedMemorySize,
                         LNG_SMEM_BYTES);
    cudaFuncSetAttribute(flash_mma_kernel,
                         cudaFuncAttributeMaxDynamicSharedMemorySize,
                         FLASH_SMEM_BYTES);

    const int M = 32768;
    const int SB = GEMM_SMEM_BYTES;

    wsplit_all_kernel<<<3328, 256>>>(Wread, Wqkv, Wo, W1, W2,
                                     wrh, wrl, wqh, wql, woh, wol,
                                     w1h, w1l, w2h, w2l);
    colsum_kernel<<<1, 512>>>(Wres);
    lif_kernel<<<32, 512>>>(x, Win, Wres, zh);

    gemm_bf16x3<<<dim3(2, 256), 256, SB>>>(zh, nullptr, wrh, wrl, bread, nullptr,
                                           h, hh, hl, M, 256, 512, 0);

    for (int l = 0; l < 2; l++) {
        gemm_bf16x3<<<dim3(6, 256), 256, SB>>>(hh, hl,
            wqh + (size_t)l * 768 * 128, wql + (size_t)l * 768 * 128,
            bqkv + l * 768, nullptr, nullptr, qh, ql_, M, 768, 256, 0);
        flash_mma_kernel<<<dim3(8, 128), 256, FLASH_SMEM_BYTES>>>(qh, ql_, ath, atl);
        // h = LN(attn @ Wo^T + bo + h) fused
        gemm_ln_bf16x3<<<512, 256, LNG_SMEM_BYTES>>>(ath, atl,
            woh + (size_t)l * 256 * 128, wol + (size_t)l * 256 * 128,
            bo + l * 256, h, g1 + l * 256, b1 + l * 256,
            h, hh, hl, 256);
        gemm_bf16x3<<<dim3(8, 256), 256, SB>>>(hh, hl,
            w1h + (size_t)l * 1024 * 128, w1l + (size_t)l * 1024 * 128,
            c1 + l * 1024, nullptr, nullptr, ffh, ffl, M, 1024, 256, 1);
        // out/h = LN(ff @ W2^T + c2 + h) fused
        gemm_ln_bf16x3<<<512, 256, LNG_SMEM_BYTES>>>(ffh, ffl,
            w2h + (size_t)l * 256 * 512, w2l + (size_t)l * 256 * 512,
            c2 + l * 256, h, g2 + l * 256, b2 + l * 256,
            (l == 1) ? out : h,
            (l == 1) ? nullptr : hh,
            (l == 1) ? nullptr : hl, 1024);
    }
}

// round 16
// speedup vs baseline: 1.0472x; 1.0472x over previous
#include <cuda_runtime.h>
#include <cstdint>

// ---------------- scratch (device globals; no allocation APIs) ----------------
__device__ float    g_h   [32768u*256u];     // fp32 hidden (residual), 32MB
__device__ float    g_tmp [32768u*256u];     // fp32 (residual-fused) GEMM out, 32MB

// bf16x2 packed (hi,lo) operand arrays; u32 = {odd<<16 | even}
__device__ uint32_t g_zh   [32u*1024u*256u];
__device__ uint32_t g_qkvh [32768u*384u], g_qkvl [32768u*384u];
__device__ uint32_t g_hh   [32768u*128u], g_hl   [32768u*128u];
__device__ uint32_t g_attnh[32768u*128u], g_attnl[32768u*128u];
__device__ uint32_t g_ffh  [32768u*512u], g_ffl  [32768u*512u];
__device__ uint32_t g_wrh  [256u*256u],   g_wrl  [256u*256u];
__device__ uint32_t g_wqh  [2u*768u*128u],g_wql  [2u*768u*128u];
__device__ uint32_t g_woh  [2u*256u*128u],g_wol  [2u*256u*128u];
__device__ uint32_t g_w1h  [2u*1024u*128u],g_w1l [2u*1024u*128u];
__device__ uint32_t g_w2h  [2u*256u*512u],g_w2l  [2u*256u*512u];

// ---------------- bf16 split helpers ----------------
__device__ __forceinline__ void split2(float e, float o, uint32_t& hi, uint32_t& lo) {
    asm("cvt.rn.bf16x2.f32 %0, %1, %2;" : "=r"(hi) : "f"(o), "f"(e));
    float he = __uint_as_float(hi << 16);
    float ho = __uint_as_float(hi & 0xffff0000u);
    asm("cvt.rn.bf16x2.f32 %0, %1, %2;" : "=r"(lo) : "f"(o - ho), "f"(e - he));
}

__device__ __forceinline__ uint32_t prmt(uint32_t a, uint32_t b, uint32_t s) {
    uint32_t r;
    asm("prmt.b32 %0, %1, %2, %3;" : "=r"(r) : "r"(a), "r"(b), "r"(s));
    return r;
}

// ---------------- fused prologue: LIF (CTAs 0..31) + weight split (32..147) ----
// LIF CTAs compute their own Wres column sum locally (identical summation order
// to the old colsum kernel -> bit-identical). wsplit CTAs run on the SMs that
// LIF leaves idle, hiding the entire weight-split cost under the LIF scan.
__global__ void __launch_bounds__(512) prologue_kernel(
    const float* __restrict__ x, const float* __restrict__ Win,
    const float* __restrict__ Wres, uint32_t* __restrict__ zh,
    const float* __restrict__ Wread, const float* __restrict__ Wqkv,
    const float* __restrict__ Wo,    const float* __restrict__ W1,
    const float* __restrict__ W2,
    uint32_t* __restrict__ wrh, uint32_t* __restrict__ wrl,
    uint32_t* __restrict__ wqh, uint32_t* __restrict__ wql,
    uint32_t* __restrict__ woh, uint32_t* __restrict__ wol,
    uint32_t* __restrict__ w1h, uint32_t* __restrict__ w1l,
    uint32_t* __restrict__ w2h, uint32_t* __restrict__ w2l)
{
    if (blockIdx.x >= 32) {
        // ---- weight split on idle SMs ----
        const int nthr = 116 * 512;
        for (int i = (blockIdx.x - 32) * 512 + threadIdx.x; i < 851968; i += nthr) {
            const float* src; uint32_t *H, *L; int off;
            if (i < 65536)        { src = Wread; H = wrh; L = wrl; off = i; }
            else if (i < 262144)  { src = Wqkv;  H = wqh; L = wql; off = i - 65536; }
            else if (i < 327680)  { src = Wo;    H = woh; L = wol; off = i - 262144; }
            else if (i < 589824)  { src = W1;    H = w1h; L = w1l; off = i - 327680; }
            else                  { src = W2;    H = w2h; L = w2l; off = i - 589824; }
            float2 v = *(const float2*)(src + 2 * off);
            split2(v.x, v.y, H[off], L[off]);
        }
        return;
    }

    // ---- LIF reservoir (R9/R14 body) ----
    const int b = blockIdx.x;
    const int r = threadIdx.x;
    const int warp = r >> 5, lane = r & 31;

    __shared__ float sWin[8][512];
    __shared__ int   s_act[512];
    __shared__ int   s_in[512];
    __shared__ int   s_wcnt[16];

    #pragma unroll
    for (int i = 0; i < 8; i++) sWin[i][r] = Win[i * 512 + r];

    // local column sum (identical order to the old colsum kernel)
    float colsum;
    {
        float s0 = 0.f, s1 = 0.f, s2 = 0.f, s3 = 0.f;
        #pragma unroll 4
        for (int rr = 0; rr < 512; rr += 4) {
            s0 += Wres[(rr + 0) * 512 + r];
            s1 += Wres[(rr + 1) * 512 + r];
            s2 += Wres[(rr + 2) * 512 + r];
            s3 += Wres[(rr + 3) * 512 + r];
        }
        colsum = (s0 + s1) + (s2 + s3);
    }

    const float* xb = x + (size_t)b * 1024 * 8;
    uint32_t* zb = zh + (size_t)b * 1024 * 256;

    float v = 0.f, isyn = 0.f;
    int zprev = 0;

    for (int t = 0; t < 1024; t++) {
        const int na = __syncthreads_count(zprev);

        float rec;
        if (na == 512) {
            rec = colsum;
        } else if (na == 0) {
            rec = 0.f;
        } else {
            unsigned bal = __ballot_sync(0xffffffffu, zprev);
            if (lane == 0) s_wcnt[warp] = __popc(bal);
            __syncthreads();
            int base_a = 0;
            #pragma unroll
            for (int w = 0; w < 16; w++) {
                int c = s_wcnt[w];
                if (w < warp) base_a += c;
            }
            int rank = __popc(bal & ((1u << lane) - 1u));
            if (zprev) s_act[base_a + rank] = r;
            else       s_in[warp * 32 - base_a + (lane - rank)] = r;
            __syncthreads();

            if (na <= 256) {
                rec = 0.f;
                for (int j = 0; j < na; j++) rec += Wres[s_act[j] * 512 + r];
            } else {
                const int ni = 512 - na;
                float a0 = 0.f, a1 = 0.f, a2 = 0.f, a3 = 0.f;
                int j = 0;
                for (; j + 4 <= ni; j += 4) {
                    a0 += Wres[s_in[j + 0] * 512 + r];
                    a1 += Wres[s_in[j + 1] * 512 + r];
                    a2 += Wres[s_in[j + 2] * 512 + r];
                    a3 += Wres[s_in[j + 3] * 512 + r];
                }
                for (; j < ni; j++) a0 += Wres[s_in[j] * 512 + r];
                rec = colsum - ((a0 + a1) + (a2 + a3));
            }
        }

        float cur = 0.f;
        #pragma unroll
        for (int i = 0; i < 8; i++) cur += xb[t * 8 + i] * sWin[i][r];

        float total = cur + rec;
        float vdec = v + 0.004f * (isyn - v);
        float idec = isyn * 0.8f;
        int z = (vdec - 0.1f) > 0.f ? 1 : 0;
        v = z ? 0.f : vdec;
        isyn = idec + total;

        int zn = __shfl_down_sync(0xffffffffu, z, 1);
        if (!(r & 1))
            zb[t * 256 + (r >> 1)] = (z ? 0x3f80u : 0u) | (zn ? 0x3f800000u : 0u);
        zprev = z;
    }
}

// ---------------- MMA helpers ----------------
__device__ __forceinline__ void mma_bf16(float* c, const uint32_t* a, const uint32_t* b) {
    asm volatile(
        "mma.sync.aligned.m16n8k16.row.col.f32.bf16.bf16.f32 "
        "{%0,%1,%2,%3},{%4,%5,%6,%7},{%8,%9},{%0,%1,%2,%3};\n"
        : "+f"(c[0]), "+f"(c[1]), "+f"(c[2]), "+f"(c[3])
        : "r"(a[0]), "r"(a[1]), "r"(a[2]), "r"(a[3]), "r"(b[0]), "r"(b[1]));
}

__device__ __forceinline__ void cp_async16(uint32_t saddr, const void* gptr) {
    asm volatile("cp.async.ca.shared.global [%0], [%1], 16;\n" :: "r"(saddr), "l"(gptr));
}

__device__ __forceinline__ void ldsm_x4(uint32_t& r0, uint32_t& r1,
                                        uint32_t& r2, uint32_t& r3, uint32_t saddr) {
    asm volatile("ldmatrix.sync.aligned.m8n8.x4.shared.b16 {%0,%1,%2,%3}, [%4];"
        : "=r"(r0), "=r"(r1), "=r"(r2), "=r"(r3) : "r"(saddr));
}

// ---------------- bf16x3 tensor-core GEMM (R12/R14 verbatim) ----------------
#define PA 20
#define MAT_U32 (128 * PA)
#define STAGE_U32 (4 * MAT_U32)
#define GEMM_SMEM_BYTES (2 * STAGE_U32 * 4)

__global__ void __launch_bounds__(256, 2) gemm_bf16x3(
    const uint32_t* __restrict__ Ah, const uint32_t* __restrict__ Al,
    const uint32_t* __restrict__ Bh, const uint32_t* __restrict__ Bl,
    const float* __restrict__ bias, const float* __restrict__ Radd,
    float* __restrict__ C, uint32_t* __restrict__ Ch, uint32_t* __restrict__ Cl,
    int M, int N, int K, int relu)
{
    extern __shared__ uint32_t smem_u[];
    const int KP   = K >> 1;
    const int tid  = threadIdx.x;
    const int lane = tid & 31;
    const int warp = tid >> 5;
    const int bm   = blockIdx.y << 7;
    const int bn   = blockIdx.x << 7;
    const int warpM = (warp >> 1) << 5;
    const int warpN = (warp & 1) << 6;
    const int g = lane >> 2;
    const int t = lane & 3;
    const bool hasAl = (Al != nullptr);

    const uint32_t sbase = (uint32_t)__cvta_generic_to_shared(smem_u);

    const int lm = lane >> 3, lr = lane & 7;
    const uint32_t aRow = (uint32_t)(warpM + ((lm & 1) << 3) + lr);
    const uint32_t aCol = (uint32_t)((lm >> 1) << 2);
    const uint32_t bRow = (uint32_t)(warpN + ((lm >> 1) << 3) + lr);
    const uint32_t bCol = (uint32_t)((lm & 1) << 2);

    float acc[2][8][4];
    #pragma unroll
    for (int mi = 0; mi < 2; mi++)
        #pragma unroll
        for (int ni = 0; ni < 8; ni++)
            #pragma unroll
            for (int r = 0; r < 4; r++) acc[mi][ni][r] = 0.f;

    const int ntiles = K >> 5;

    auto issue = [&](int kt, int s) {
        uint32_t st = sbase + (uint32_t)(s * STAGE_U32) * 4u;
        #pragma unroll
        for (int i = 0; i < 2; i++) {
            int slot = tid + (i << 8);
            int row = slot >> 2, c4 = (slot & 3) << 2;
            size_t go = (size_t)row * KP + kt * 16 + c4;
            uint32_t so = (uint32_t)(row * PA + c4) * 4u;
            cp_async16(st + 0 * MAT_U32 * 4u + so, Ah + (size_t)bm * KP + go);
            if (hasAl)
                cp_async16(st + 1 * MAT_U32 * 4u + so, Al + (size_t)bm * KP + go);
            cp_async16(st + 2 * MAT_U32 * 4u + so, Bh + (size_t)bn * KP + go);
            cp_async16(st + 3 * MAT_U32 * 4u + so, Bl + (size_t)bn * KP + go);
        }
        asm volatile("cp.async.commit_group;\n");
    };

    issue(0, 0);
    if (ntiles > 1) issue(1, 1);

    for (int kt = 0; kt < ntiles; kt++) {
        const int s = kt & 1;
        if (kt + 2 < ntiles)
            asm volatile("cp.async.wait_group 1;\n" ::: "memory");
        else
            asm volatile("cp.async.wait_group 0;\n" ::: "memory");
        __syncthreads();

        const uint32_t stage = sbase + (uint32_t)(s * STAGE_U32) * 4u;
        const uint32_t aBaseH = stage + (aRow * PA + aCol) * 4u;
        const uint32_t bBaseH = stage + 2u * MAT_U32 * 4u + (bRow * PA + bCol) * 4u;

        #pragma unroll
        for (int ch = 0; ch < 2; ch++) {
            const uint32_t cc = (uint32_t)(ch << 3) * 4u;

            uint32_t ah[2][4], alr[2][4];
            #pragma unroll
            for (int mi = 0; mi < 2; mi++) {
                const uint32_t aa = aBaseH + (uint32_t)(mi * 16 * PA) * 4u + cc;
                ldsm_x4(ah[mi][0], ah[mi][1], ah[mi][2], ah[mi][3], aa);
                if (hasAl)
                    ldsm_x4(alr[mi][0], alr[mi][1], alr[mi][2], alr[mi][3],
                            aa + (uint32_t)MAT_U32 * 4u);
            }

            #pragma unroll
            for (int p = 0; p < 4; p++) {
                const uint32_t ba = bBaseH + (uint32_t)(p * 16 * PA) * 4u + cc;
                uint32_t b0h[2], b1h[2], b0l[2], b1l[2];
                ldsm_x4(b0h[0], b0h[1], b1h[0], b1h[1], ba);
                ldsm_x4(b0l[0], b0l[1], b1l[0], b1l[1], ba + (uint32_t)MAT_U32 * 4u);

                const int n0 = 2 * p, n1 = 2 * p + 1;
                mma_bf16(acc[0][n0], ah[0], b0h);
                mma_bf16(acc[0][n0], ah[0], b0l);
                mma_bf16(acc[1][n0], ah[1], b0h);
                mma_bf16(acc[1][n0], ah[1], b0l);
                mma_bf16(acc[0][n1], ah[0], b1h);
                mma_bf16(acc[0][n1], ah[0], b1l);
                mma_bf16(acc[1][n1], ah[1], b1h);
                mma_bf16(acc[1][n1], ah[1], b1l);
                if (hasAl) {
                    mma_bf16(acc[0][n0], alr[0], b0h);
                    mma_bf16(acc[1][n0], alr[1], b0h);
                    mma_bf16(acc[0][n1], alr[0], b1h);
                    mma_bf16(acc[1][n1], alr[1], b1h);
                }
            }
        }

        __syncthreads();
        if (kt + 2 < ntiles) issue(kt + 2, s);
    }

    const int cq = t << 1;
    #pragma unroll
    for (int ni = 0; ni < 8; ni++) {
        const int col = bn + warpN + (ni << 3) + cq;
        const float b0 = bias[col], b1 = bias[col + 1];
        #pragma unroll
        for (int mi = 0; mi < 2; mi++) {
            const int row0 = bm + warpM + (mi << 4) + g;
            float2 v0, v1;
            v0.x = acc[mi][ni][0] + b0; v0.y = acc[mi][ni][1] + b1;
            v1.x = acc[mi][ni][2] + b0; v1.y = acc[mi][ni][3] + b1;
            if (Radd) {
                float2 r0 = *(const float2*)&Radd[(size_t)row0 * N + col];
                float2 r1 = *(const float2*)&Radd[(size_t)(row0 + 8) * N + col];
                v0.x += r0.x; v0.y += r0.y;
                v1.x += r1.x; v1.y += r1.y;
            }
            if (relu) {
                v0.x = fmaxf(v0.x, 0.f); v0.y = fmaxf(v0.y, 0.f);
                v1.x = fmaxf(v1.x, 0.f); v1.y = fmaxf(v1.y, 0.f);
            }
            if (C) {
                *(float2*)&C[(size_t)row0 * N + col] = v0;
                *(float2*)&C[(size_t)(row0 + 8) * N + col] = v1;
            }
            if (Ch) {
                const int NP = N >> 1;
                const int pc = col >> 1;
                uint32_t ph, pl;
                split2(v0.x, v0.y, ph, pl);
                Ch[(size_t)row0 * NP + pc] = ph;
                Cl[(size_t)row0 * NP + pc] = pl;
                split2(v1.x, v1.y, ph, pl);
                Ch[(size_t)(row0 + 8) * NP + pc] = ph;
                Cl[(size_t)(row0 + 8) * NP + pc] = pl;
            }
        }
    }
}

// ---------------- bf16x3 MMA flash attention (R14 verbatim) --------------------
#define FLASH_SMEM_BYTES (18176 * 4)

__global__ void __launch_bounds__(256, 2) flash_mma_kernel(
    const uint32_t* __restrict__ qkvh, const uint32_t* __restrict__ qkvl,
    uint32_t* __restrict__ attnh, uint32_t* __restrict__ attnl)
{
    extern __shared__ uint32_t S[];
    uint32_t* KPh = S;
    uint32_t* KPl = S + 2304;
    uint32_t* VPh = S + 4608;
    uint32_t* VPl = S + 6784;
    uint32_t* Ph  = S + 8960;
    uint32_t* Pl  = S + 13568;

    const int tid  = threadIdx.x;
    const int lane = tid & 31;
    const int w    = tid >> 5;
    const int g    = lane >> 2;
    const int t    = lane & 3;
    const int qb   = blockIdx.x;
    const int bh   = blockIdx.y;
    const int b    = bh >> 2, h = bh & 3;

    const uint32_t sbase = (uint32_t)__cvta_generic_to_shared(S);
    const uint32_t* kph = qkvh + (size_t)b * 1024 * 384 + 128 + h * 32;
    const uint32_t* kpl = qkvl + (size_t)b * 1024 * 384 + 128 + h * 32;
    const uint32_t* vph = qkvh + (size_t)b * 1024 * 384 + 256 + h * 32;
    const uint32_t* vpl = qkvl + (size_t)b * 1024 * 384 + 256 + h * 32;

    const int wr = w * 16;
    const float SCALE = 0.125f;
    const float L2E   = 1.4426950408889634f;

    uint32_t qh[4][4], ql[4][4];
    {
        const size_t q0 = (size_t)(b * 1024 + qb * 128 + wr + g) * 384 + h * 32;
        const size_t q1 = q0 + (size_t)8 * 384;
        #pragma unroll
        for (int c = 0; c < 4; c++) {
            const int p = c * 8 + t;
            qh[c][0] = qkvh[q0 + p];     ql[c][0] = qkvl[q0 + p];
            qh[c][1] = qkvh[q1 + p];     ql[c][1] = qkvl[q1 + p];
            qh[c][2] = qkvh[q0 + p + 4]; ql[c][2] = qkvl[q0 + p + 4];
            qh[c][3] = qkvh[q1 + p + 4]; ql[c][3] = qkvl[q1 + p + 4];
        }
    }

    float oacc[8][4];
    #pragma unroll
    for (int nt = 0; nt < 8; nt++)
        #pragma unroll
        for (int r = 0; r < 4; r++) oacc[nt][r] = 0.f;
    float m0 = -1e30f, m1 = -1e30f, l0 = 0.f, l1 = 0.f;

    for (int kb = 0; kb < 16; kb++) {
        #pragma unroll
        for (int i = 0; i < 2; i++) {
            const int idx = i * 256 + tid;
            const int row = idx >> 3, q4 = (idx & 7) << 2;
            const size_t go = (size_t)(kb * 64 + row) * 384 + q4;
            const uint32_t so = (uint32_t)(row * 36 + q4) * 4u;
            cp_async16(sbase + so, kph + go);
            cp_async16(sbase + 2304u * 4u + so, kpl + go);
        }
        asm volatile("cp.async.commit_group;\n");

        {
            const int k2 = tid >> 3, j = tid & 7;
            const size_t r0 = (size_t)(kb * 64 + 2 * k2) * 384 + 4 * j;
            uint4 Ahv = *(const uint4*)&vph[r0];
            uint4 Bhv = *(const uint4*)&vph[r0 + 384];
            uint4 Alv = *(const uint4*)&vpl[r0];
            uint4 Blv = *(const uint4*)&vpl[r0 + 384];

            uint4 o0, o1;
            o0.x = prmt(Ahv.x, Bhv.x, 0x5410u); o0.y = prmt(Ahv.x, Bhv.x, 0x7632u);
            o0.z = prmt(Ahv.y, Bhv.y, 0x5410u); o0.w = prmt(Ahv.y, Bhv.y, 0x7632u);
            o1.x = prmt(Ahv.z, Bhv.z, 0x5410u); o1.y = prmt(Ahv.z, Bhv.z, 0x7632u);
            o1.z = prmt(Ahv.w, Bhv.w, 0x5410u); o1.w = prmt(Ahv.w, Bhv.w, 0x7632u);
            *(uint4*)&VPh[k2 * 68 + 8 * j]     = o0;
            *(uint4*)&VPh[k2 * 68 + 8 * j + 4] = o1;

            o0.x = prmt(Alv.x, Blv.x, 0x5410u); o0.y = prmt(Alv.x, Blv.x, 0x7632u);
            o0.z = prmt(Alv.y, Blv.y, 0x5410u); o0.w = prmt(Alv.y, Blv.y, 0x7632u);
            o1.x = prmt(Alv.z, Blv.z, 0x5410u); o1.y = prmt(Alv.z, Blv.z, 0x7632u);
            o1.z = prmt(Alv.w, Blv.w, 0x5410u); o1.w = prmt(Alv.w, Blv.w, 0x7632u);
            *(uint4*)&VPl[k2 * 68 + 8 * j]     = o0;
            *(uint4*)&VPl[k2 * 68 + 8 * j + 4] = o1;
        }
        asm volatile("cp.async.wait_group 0;\n" ::: "memory");
        __syncthreads();

        float sc[8][4];
        #pragma unroll
        for (int nt = 0; nt < 8; nt++)
            #pragma unroll
            for (int r = 0; r < 4; r++) sc[nt][r] = 0.f;

        #pragma unroll
        for (int c = 0; c < 4; c++) {
            const int c8 = c * 8 + t;
            #pragma unroll
            for (int nt = 0; nt < 8; nt++) {
                const uint32_t* kr = &KPh[(nt * 8 + g) * 36];
                const uint32_t* kl = &KPl[(nt * 8 + g) * 36];
                uint32_t bh2[2] = { kr[c8], kr[c8 + 4] };
                uint32_t bl2[2] = { kl[c8], kl[c8 + 4] };
                mma_bf16(sc[nt], qh[c], bh2);
                mma_bf16(sc[nt], qh[c], bl2);
                mma_bf16(sc[nt], ql[c], bh2);
            }
        }

        float mb0 = -1e30f, mb1 = -1e30f;
        #pragma unroll
        for (int nt = 0; nt < 8; nt++) {
            sc[nt][0] *= SCALE; sc[nt][1] *= SCALE;
            sc[nt][2] *= SCALE; sc[nt][3] *= SCALE;
            mb0 = fmaxf(mb0, fmaxf(sc[nt][0], sc[nt][1]));
            mb1 = fmaxf(mb1, fmaxf(sc[nt][2], sc[nt][3]));
        }
        #pragma unroll
        for (int off = 1; off <= 2; off <<= 1) {
            mb0 = fmaxf(mb0, __shfl_xor_sync(0xffffffffu, mb0, off));
            mb1 = fmaxf(mb1, __shfl_xor_sync(0xffffffffu, mb1, off));
        }
        const float mn0 = fmaxf(m0, mb0);
        const float mn1 = fmaxf(m1, mb1);
        const float c0 = exp2f((m0 - mn0) * L2E);
        const float c1 = exp2f((m1 - mn1) * L2E);
        l0 *= c0; l1 *= c1;
        #pragma unroll
        for (int nt = 0; nt < 8; nt++) {
            oacc[nt][0] *= c0; oacc[nt][1] *= c0;
            oacc[nt][2] *= c1; oacc[nt][3] *= c1;
        }
        #pragma unroll
        for (int nt = 0; nt < 8; nt++) {
            sc[nt][0] = exp2f((sc[nt][0] - mn0) * L2E);
            sc[nt][1] = exp2f((sc[nt][1] - mn0) * L2E);
            sc[nt][2] = exp2f((sc[nt][2] - mn1) * L2E);
            sc[nt][3] = exp2f((sc[nt][3] - mn1) * L2E);
            l0 += sc[nt][0] + sc[nt][1];
            l1 += sc[nt][2] + sc[nt][3];
        }
        m0 = mn0; m1 = mn1;

        #pragma unroll
        for (int nt = 0; nt < 8; nt++) {
            const int pc = nt * 4 + t;
            split2(sc[nt][0], sc[nt][1], Ph[(wr + g) * 36 + pc], Pl[(wr + g) * 36 + pc]);
            split2(sc[nt][2], sc[nt][3], Ph[(wr + g + 8) * 36 + pc], Pl[(wr + g + 8) * 36 + pc]);
        }
        __syncwarp();

        #pragma unroll
        for (int c = 0; c < 4; c++) {
            const int c8 = c * 8 + t;
            uint32_t ah2[4], al2[4];
            ah2[0] = Ph[(wr + g) * 36 + c8];
            ah2[1] = Ph[(wr + g + 8) * 36 + c8];
            ah2[2] = Ph[(wr + g) * 36 + c8 + 4];
            ah2[3] = Ph[(wr + g + 8) * 36 + c8 + 4];
            al2[0] = Pl[(wr + g) * 36 + c8];
            al2[1] = Pl[(wr + g + 8) * 36 + c8];
            al2[2] = Pl[(wr + g) * 36 + c8 + 4];
            al2[3] = Pl[(wr + g + 8) * 36 + c8 + 4];
            #pragma unroll
            for (int nt = 0; nt < 8; nt++) {
                const int vc = nt * 8 + g;
                uint32_t bh2[2] = { VPh[(c8) * 68 + vc], VPh[(c8 + 4) * 68 + vc] };
                uint32_t bl2[2] = { VPl[(c8) * 68 + vc], VPl[(c8 + 4) * 68 + vc] };
                mma_bf16(oacc[nt], ah2, bh2);
                mma_bf16(oacc[nt], ah2, bl2);
                mma_bf16(oacc[nt], al2, bh2);
            }
        }
        __syncthreads();
    }

    #pragma unroll
    for (int off = 1; off <= 2; off <<= 1) {
        l0 += __shfl_xor_sync(0xffffffffu, l0, off);
        l1 += __shfl_xor_sync(0xffffffffu, l1, off);
    }
    const float inv0 = 1.f / l0;
    const float inv1 = 1.f / l1;

    const int row0 = b * 1024 + qb * 128 + wr + g;
    #pragma unroll
    for (int nt = 0; nt < 8; nt++) {
        const int pc = h * 32 + (nt << 2) + t;
        uint32_t ph, pl;
        split2(oacc[nt][0] * inv0, oacc[nt][1] * inv0, ph, pl);
        attnh[(size_t)row0 * 128 + pc] = ph;
        attnl[(size_t)row0 * 128 + pc] = pl;
        split2(oacc[nt][2] * inv1, oacc[nt][3] * inv1, ph, pl);
        attnh[(size_t)(row0 + 8) * 128 + pc] = ph;
        attnl[(size_t)(row0 + 8) * 128 + pc] = pl;
    }
}

// ---------------- layernorm (R14 verbatim) ----------------
__global__ void __launch_bounds__(256) ln_kernel(
    const float* __restrict__ xa,
    const float* __restrict__ g, const float* __restrict__ bt,
    float* __restrict__ out, uint32_t* __restrict__ oh, uint32_t* __restrict__ ol)
{
    const int warp = threadIdx.x >> 5, lane = threadIdx.x & 31;
    const size_t row = (size_t)blockIdx.x * 8 + warp;
    const float* pa = xa + row * 256 + lane * 8;

    float v[8];
    *(float4*)&v[0] = *(const float4*)pa;
    *(float4*)&v[4] = *(const float4*)(pa + 4);

    float s = ((v[0] + v[1]) + (v[2] + v[3])) + ((v[4] + v[5]) + (v[6] + v[7]));
    #pragma unroll
    for (int off = 16; off > 0; off >>= 1) s += __shfl_xor_sync(0xffffffffu, s, off);
    float mean = s * (1.f / 256.f);

    float vs = 0.f;
    #pragma unroll
    for (int i = 0; i < 8; i++) { float d = v[i] - mean; vs += d * d; }
    #pragma unroll
    for (int off = 16; off > 0; off >>= 1) vs += __shfl_xor_sync(0xffffffffu, vs, off);
    float inv = 1.f / sqrtf(vs * (1.f / 256.f) + 1e-5f);

    float gg[8], bb[8];
    *(float4*)&gg[0] = *(const float4*)(g + lane * 8);
    *(float4*)&gg[4] = *(const float4*)(g + lane * 8 + 4);
    *(float4*)&bb[0] = *(const float4*)(bt + lane * 8);
    *(float4*)&bb[4] = *(const float4*)(bt + lane * 8 + 4);

    float o[8];
    #pragma unroll
    for (int i = 0; i < 8; i++) o[i] = (v[i] - mean) * inv * gg[i] + bb[i];

    float* po = out + row * 256 + lane * 8;
    *(float4*)po = *(float4*)&o[0];
    *(float4*)(po + 4) = *(float4*)&o[4];

    if (oh) {
        uint32_t ph[4], pl[4];
        #pragma unroll
        for (int j = 0; j < 4; j++) split2(o[2 * j], o[2 * j + 1], ph[j], pl[j]);
        *(uint4*)&oh[row * 128 + lane * 4] = *(uint4*)ph;
        *(uint4*)&ol[row * 128 + lane * 4] = *(uint4*)pl;
    }
}

// -------------------------------- launch ---------------------------------------
extern "C" void kernel_launch(void* const* d_in, const int* in_sizes, int n_in,
                              void* d_out, int out_size)
{
    const float* x     = (const float*)d_in[0];
    const float* Win   = (const float*)d_in[1];
    const float* Wres  = (const float*)d_in[2];
    const float* Wread = (const float*)d_in[3];
    const float* bread = (const float*)d_in[4];
    const float* Wqkv  = (const float*)d_in[5];
    const float* bqkv  = (const float*)d_in[6];
    const float* Wo    = (const float*)d_in[7];
    const float* bo    = (const float*)d_in[8];
    const float* g1    = (const float*)d_in[9];
    const float* b1    = (const float*)d_in[10];
    const float* g2    = (const float*)d_in[11];
    const float* b2    = (const float*)d_in[12];
    const float* W1    = (const float*)d_in[13];
    const float* c1    = (const float*)d_in[14];
    const float* W2    = (const float*)d_in[15];
    const float* c2    = (const float*)d_in[16];
    float* out = (float*)d_out;

    float *h, *tmp;
    uint32_t *zh, *qh, *ql_, *hh, *hl, *ath, *atl, *ffh, *ffl;
    uint32_t *wrh, *wrl, *wqh, *wql, *woh, *wol, *w1h, *w1l, *w2h, *w2l;
    cudaGetSymbolAddress((void**)&h,   g_h);
    cudaGetSymbolAddress((void**)&tmp, g_tmp);
    cudaGetSymbolAddress((void**)&zh,  g_zh);
    cudaGetSymbolAddress((void**)&qh,  g_qkvh);
    cudaGetSymbolAddress((void**)&ql_, g_qkvl);
    cudaGetSymbolAddress((void**)&hh,  g_hh);
    cudaGetSymbolAddress((void**)&hl,  g_hl);
    cudaGetSymbolAddress((void**)&ath, g_attnh);
    cudaGetSymbolAddress((void**)&atl, g_attnl);
    cudaGetSymbolAddress((void**)&ffh, g_ffh);
    cudaGetSymbolAddress((void**)&ffl, g_ffl);
    cudaGetSymbolAddress((void**)&wrh, g_wrh);
    cudaGetSymbolAddress((void**)&wrl, g_wrl);
    cudaGetSymbolAddress((void**)&wqh, g_wqh);
    cudaGetSymbolAddress((void**)&wql, g_wql);
    cudaGetSymbolAddress((void**)&woh, g_woh);
    cudaGetSymbolAddress((void**)&wol, g_wol);
    cudaGetSymbolAddress((void**)&w1h, g_w1h);
    cudaGetSymbolAddress((void**)&w1l, g_w1l);
    cudaGetSymbolAddress((void**)&w2h, g_w2h);
    cudaGetSymbolAddress((void**)&w2l, g_w2l);

    cudaFuncSetAttribute(gemm_bf16x3,
                         cudaFuncAttributeMaxDynamicSharedMemorySize,
                         GEMM_SMEM_BYTES);
    cudaFuncSetAttribute(flash_mma_kernel,
                         cudaFuncAttributeMaxDynamicSharedMemorySize,
                         FLASH_SMEM_BYTES);

    const int M = 32768;
    const int SB = GEMM_SMEM_BYTES;

    // fused prologue: LIF (32 CTAs) + weight split (116 CTAs) in one launch
    prologue_kernel<<<148, 512>>>(x, Win, Wres, zh,
                                  Wread, Wqkv, Wo, W1, W2,
                                  wrh, wrl, wqh, wql, woh, wol,
                                  w1h, w1l, w2h, w2l);

    gemm_bf16x3<<<dim3(2, 256), 256, SB>>>(zh, nullptr, wrh, wrl, bread, nullptr,
                                           h, hh, hl, M, 256, 512, 0);

    for (int l = 0; l < 2; l++) {
        gemm_bf16x3<<<dim3(6, 256), 256, SB>>>(hh, hl,
            wqh + (size_t)l * 768 * 128, wql + (size_t)l * 768 * 128,
            bqkv + l * 768, nullptr, nullptr, qh, ql_, M, 768, 256, 0);
        flash_mma_kernel<<<dim3(8, 128), 256, FLASH_SMEM_BYTES>>>(qh, ql_, ath, atl);
        gemm_bf16x3<<<dim3(2, 256), 256, SB>>>(ath, atl,
            woh + (size_t)l * 256 * 128, wol + (size_t)l * 256 * 128,
            bo + l * 256, h, tmp, nullptr, nullptr, M, 256, 256, 0);
        ln_kernel<<<4096, 256>>>(tmp, g1 + l * 256, b1 + l * 256, h, hh, hl);
        gemm_bf16x3<<<dim3(8, 256), 256, SB>>>(hh, hl,
            w1h + (size_t)l * 1024 * 128, w1l + (size_t)l * 1024 * 128,
            c1 + l * 1024, nullptr, nullptr, ffh, ffl, M, 1024, 256, 1);
        gemm_bf16x3<<<dim3(2, 256), 256, SB>>>(ffh, ffl,
            w2h + (size_t)l * 256 * 512, w2l + (size_t)l * 256 * 512,
            c2 + l * 256, h, tmp, nullptr, nullptr, M, 256, 1024, 0);
        ln_kernel<<<4096, 256>>>(tmp, g2 + l * 256, b2 + l * 256,
                                 (l == 1) ? out : h,
                                 (l == 1) ? nullptr : hh,
                                 (l == 1) ? nullptr : hl);
    }
}

// round 17
// speedup vs baseline: 1.0616x; 1.0137x over previous
#include <cuda_runtime.h>
#include <cstdint>

// ---------------- scratch (device globals; no allocation APIs) ----------------
__device__ float    g_h   [32768u*256u];     // fp32 hidden (residual), 32MB
__device__ float    g_tmp [32768u*256u];     // fp32 (residual-fused) GEMM out, 32MB

// bf16x2 packed (hi,lo) operand arrays; u32 = {odd<<16 | even}
__device__ uint32_t g_zh   [32u*1024u*256u];
__device__ uint32_t g_qkvh [32768u*384u], g_qkvl [32768u*384u];
__device__ uint32_t g_hh   [32768u*128u], g_hl   [32768u*128u];
__device__ uint32_t g_attnh[32768u*128u], g_attnl[32768u*128u];
__device__ uint32_t g_ffh  [32768u*512u], g_ffl  [32768u*512u];
__device__ uint32_t g_wrh  [256u*256u],   g_wrl  [256u*256u];
__device__ uint32_t g_wqh  [2u*768u*128u],g_wql  [2u*768u*128u];
__device__ uint32_t g_woh  [2u*256u*128u],g_wol  [2u*256u*128u];
__device__ uint32_t g_w1h  [2u*1024u*128u],g_w1l [2u*1024u*128u];
__device__ uint32_t g_w2h  [2u*256u*512u],g_w2l  [2u*256u*512u];

// ---------------- bf16 split helpers ----------------
__device__ __forceinline__ void split2(float e, float o, uint32_t& hi, uint32_t& lo) {
    asm("cvt.rn.bf16x2.f32 %0, %1, %2;" : "=r"(hi) : "f"(o), "f"(e));
    float he = __uint_as_float(hi << 16);
    float ho = __uint_as_float(hi & 0xffff0000u);
    asm("cvt.rn.bf16x2.f32 %0, %1, %2;" : "=r"(lo) : "f"(o - ho), "f"(e - he));
}

__device__ __forceinline__ uint32_t prmt(uint32_t a, uint32_t b, uint32_t s) {
    uint32_t r;
    asm("prmt.b32 %0, %1, %2, %3;" : "=r"(r) : "r"(a), "r"(b), "r"(s));
    return r;
}

// ---------------- fused prologue: LIF (CTAs 0..31) + weight split (32..147) ----
__global__ void __launch_bounds__(512) prologue_kernel(
    const float* __restrict__ x, const float* __restrict__ Win,
    const float* __restrict__ Wres, uint32_t* __restrict__ zh,
    const float* __restrict__ Wread, const float* __restrict__ Wqkv,
    const float* __restrict__ Wo,    const float* __restrict__ W1,
    const float* __restrict__ W2,
    uint32_t* __restrict__ wrh, uint32_t* __restrict__ wrl,
    uint32_t* __restrict__ wqh, uint32_t* __restrict__ wql,
    uint32_t* __restrict__ woh, uint32_t* __restrict__ wol,
    uint32_t* __restrict__ w1h, uint32_t* __restrict__ w1l,
    uint32_t* __restrict__ w2h, uint32_t* __restrict__ w2l)
{
    if (blockIdx.x >= 32) {
        const int nthr = 116 * 512;
        for (int i = (blockIdx.x - 32) * 512 + threadIdx.x; i < 851968; i += nthr) {
            const float* src; uint32_t *H, *L; int off;
            if (i < 65536)        { src = Wread; H = wrh; L = wrl; off = i; }
            else if (i < 262144)  { src = Wqkv;  H = wqh; L = wql; off = i - 65536; }
            else if (i < 327680)  { src = Wo;    H = woh; L = wol; off = i - 262144; }
            else if (i < 589824)  { src = W1;    H = w1h; L = w1l; off = i - 327680; }
            else                  { src = W2;    H = w2h; L = w2l; off = i - 589824; }
            float2 v = *(const float2*)(src + 2 * off);
            split2(v.x, v.y, H[off], L[off]);
        }
        return;
    }

    const int b = blockIdx.x;
    const int r = threadIdx.x;
    const int warp = r >> 5, lane = r & 31;

    __shared__ float sWin[8][512];
    __shared__ int   s_act[512];
    __shared__ int   s_in[512];
    __shared__ int   s_wcnt[16];

    #pragma unroll
    for (int i = 0; i < 8; i++) sWin[i][r] = Win[i * 512 + r];

    float colsum;
    {
        float s0 = 0.f, s1 = 0.f, s2 = 0.f, s3 = 0.f;
        #pragma unroll 4
        for (int rr = 0; rr < 512; rr += 4) {
            s0 += Wres[(rr + 0) * 512 + r];
            s1 += Wres[(rr + 1) * 512 + r];
            s2 += Wres[(rr + 2) * 512 + r];
            s3 += Wres[(rr + 3) * 512 + r];
        }
        colsum = (s0 + s1) + (s2 + s3);
    }

    const float* xb = x + (size_t)b * 1024 * 8;
    uint32_t* zb = zh + (size_t)b * 1024 * 256;

    float v = 0.f, isyn = 0.f;
    int zprev = 0;

    for (int t = 0; t < 1024; t++) {
        const int na = __syncthreads_count(zprev);

        float rec;
        if (na == 512) {
            rec = colsum;
        } else if (na == 0) {
            rec = 0.f;
        } else {
            unsigned bal = __ballot_sync(0xffffffffu, zprev);
            if (lane == 0) s_wcnt[warp] = __popc(bal);
            __syncthreads();
            int base_a = 0;
            #pragma unroll
            for (int w = 0; w < 16; w++) {
                int c = s_wcnt[w];
                if (w < warp) base_a += c;
            }
            int rank = __popc(bal & ((1u << lane) - 1u));
            if (zprev) s_act[base_a + rank] = r;
            else       s_in[warp * 32 - base_a + (lane - rank)] = r;
            __syncthreads();

            if (na <= 256) {
                rec = 0.f;
                for (int j = 0; j < na; j++) rec += Wres[s_act[j] * 512 + r];
            } else {
                const int ni = 512 - na;
                float a0 = 0.f, a1 = 0.f, a2 = 0.f, a3 = 0.f;
                int j = 0;
                for (; j + 4 <= ni; j += 4) {
                    a0 += Wres[s_in[j + 0] * 512 + r];
                    a1 += Wres[s_in[j + 1] * 512 + r];
                    a2 += Wres[s_in[j + 2] * 512 + r];
                    a3 += Wres[s_in[j + 3] * 512 + r];
                }
                for (; j < ni; j++) a0 += Wres[s_in[j] * 512 + r];
                rec = colsum - ((a0 + a1) + (a2 + a3));
            }
        }

        float cur = 0.f;
        #pragma unroll
        for (int i = 0; i < 8; i++) cur += xb[t * 8 + i] * sWin[i][r];

        float total = cur + rec;
        float vdec = v + 0.004f * (isyn - v);
        float idec = isyn * 0.8f;
        int z = (vdec - 0.1f) > 0.f ? 1 : 0;
        v = z ? 0.f : vdec;
        isyn = idec + total;

        int zn = __shfl_down_sync(0xffffffffu, z, 1);
        if (!(r & 1))
            zb[t * 256 + (r >> 1)] = (z ? 0x3f80u : 0u) | (zn ? 0x3f800000u : 0u);
        zprev = z;
    }
}

// ---------------- MMA helpers ----------------
__device__ __forceinline__ void mma_bf16(float* c, const uint32_t* a, const uint32_t* b) {
    asm volatile(
        "mma.sync.aligned.m16n8k16.row.col.f32.bf16.bf16.f32 "
        "{%0,%1,%2,%3},{%4,%5,%6,%7},{%8,%9},{%0,%1,%2,%3};\n"
        : "+f"(c[0]), "+f"(c[1]), "+f"(c[2]), "+f"(c[3])
        : "r"(a[0]), "r"(a[1]), "r"(a[2]), "r"(a[3]), "r"(b[0]), "r"(b[1]));
}

__device__ __forceinline__ void cp_async16(uint32_t saddr, const void* gptr) {
    asm volatile("cp.async.ca.shared.global [%0], [%1], 16;\n" :: "r"(saddr), "l"(gptr));
}

__device__ __forceinline__ void ldsm_x4(uint32_t& r0, uint32_t& r1,
                                        uint32_t& r2, uint32_t& r3, uint32_t saddr) {
    asm volatile("ldmatrix.sync.aligned.m8n8.x4.shared.b16 {%0,%1,%2,%3}, [%4];"
        : "=r"(r0), "=r"(r1), "=r"(r2), "=r"(r3) : "r"(saddr));
}

// ---------------- bf16x3 tensor-core GEMM (R12/R14 verbatim) ----------------
#define PA 20
#define MAT_U32 (128 * PA)
#define STAGE_U32 (4 * MAT_U32)
#define GEMM_SMEM_BYTES (2 * STAGE_U32 * 4)

__global__ void __launch_bounds__(256, 2) gemm_bf16x3(
    const uint32_t* __restrict__ Ah, const uint32_t* __restrict__ Al,
    const uint32_t* __restrict__ Bh, const uint32_t* __restrict__ Bl,
    const float* __restrict__ bias, const float* __restrict__ Radd,
    float* __restrict__ C, uint32_t* __restrict__ Ch, uint32_t* __restrict__ Cl,
    int M, int N, int K, int relu)
{
    extern __shared__ uint32_t smem_u[];
    const int KP   = K >> 1;
    const int tid  = threadIdx.x;
    const int lane = tid & 31;
    const int warp = tid >> 5;
    const int bm   = blockIdx.y << 7;
    const int bn   = blockIdx.x << 7;
    const int warpM = (warp >> 1) << 5;
    const int warpN = (warp & 1) << 6;
    const int g = lane >> 2;
    const int t = lane & 3;
    const bool hasAl = (Al != nullptr);

    const uint32_t sbase = (uint32_t)__cvta_generic_to_shared(smem_u);

    const int lm = lane >> 3, lr = lane & 7;
    const uint32_t aRow = (uint32_t)(warpM + ((lm & 1) << 3) + lr);
    const uint32_t aCol = (uint32_t)((lm >> 1) << 2);
    const uint32_t bRow = (uint32_t)(warpN + ((lm >> 1) << 3) + lr);
    const uint32_t bCol = (uint32_t)((lm & 1) << 2);

    float acc[2][8][4];
    #pragma unroll
    for (int mi = 0; mi < 2; mi++)
        #pragma unroll
        for (int ni = 0; ni < 8; ni++)
            #pragma unroll
            for (int r = 0; r < 4; r++) acc[mi][ni][r] = 0.f;

    const int ntiles = K >> 5;

    auto issue = [&](int kt, int s) {
        uint32_t st = sbase + (uint32_t)(s * STAGE_U32) * 4u;
        #pragma unroll
        for (int i = 0; i < 2; i++) {
            int slot = tid + (i << 8);
            int row = slot >> 2, c4 = (slot & 3) << 2;
            size_t go = (size_t)row * KP + kt * 16 + c4;
            uint32_t so = (uint32_t)(row * PA + c4) * 4u;
            cp_async16(st + 0 * MAT_U32 * 4u + so, Ah + (size_t)bm * KP + go);
            if (hasAl)
                cp_async16(st + 1 * MAT_U32 * 4u + so, Al + (size_t)bm * KP + go);
            cp_async16(st + 2 * MAT_U32 * 4u + so, Bh + (size_t)bn * KP + go);
            cp_async16(st + 3 * MAT_U32 * 4u + so, Bl + (size_t)bn * KP + go);
        }
        asm volatile("cp.async.commit_group;\n");
    };

    issue(0, 0);
    if (ntiles > 1) issue(1, 1);

    for (int kt = 0; kt < ntiles; kt++) {
        const int s = kt & 1;
        if (kt + 2 < ntiles)
            asm volatile("cp.async.wait_group 1;\n" ::: "memory");
        else
            asm volatile("cp.async.wait_group 0;\n" ::: "memory");
        __syncthreads();

        const uint32_t stage = sbase + (uint32_t)(s * STAGE_U32) * 4u;
        const uint32_t aBaseH = stage + (aRow * PA + aCol) * 4u;
        const uint32_t bBaseH = stage + 2u * MAT_U32 * 4u + (bRow * PA + bCol) * 4u;

        #pragma unroll
        for (int ch = 0; ch < 2; ch++) {
            const uint32_t cc = (uint32_t)(ch << 3) * 4u;

            uint32_t ah[2][4], alr[2][4];
            #pragma unroll
            for (int mi = 0; mi < 2; mi++) {
                const uint32_t aa = aBaseH + (uint32_t)(mi * 16 * PA) * 4u + cc;
                ldsm_x4(ah[mi][0], ah[mi][1], ah[mi][2], ah[mi][3], aa);
                if (hasAl)
                    ldsm_x4(alr[mi][0], alr[mi][1], alr[mi][2], alr[mi][3],
                            aa + (uint32_t)MAT_U32 * 4u);
            }

            #pragma unroll
            for (int p = 0; p < 4; p++) {
                const uint32_t ba = bBaseH + (uint32_t)(p * 16 * PA) * 4u + cc;
                uint32_t b0h[2], b1h[2], b0l[2], b1l[2];
                ldsm_x4(b0h[0], b0h[1], b1h[0], b1h[1], ba);
                ldsm_x4(b0l[0], b0l[1], b1l[0], b1l[1], ba + (uint32_t)MAT_U32 * 4u);

                const int n0 = 2 * p, n1 = 2 * p + 1;
                mma_bf16(acc[0][n0], ah[0], b0h);
                mma_bf16(acc[0][n0], ah[0], b0l);
                mma_bf16(acc[1][n0], ah[1], b0h);
                mma_bf16(acc[1][n0], ah[1], b0l);
                mma_bf16(acc[0][n1], ah[0], b1h);
                mma_bf16(acc[0][n1], ah[0], b1l);
                mma_bf16(acc[1][n1], ah[1], b1h);
                mma_bf16(acc[1][n1], ah[1], b1l);
                if (hasAl) {
                    mma_bf16(acc[0][n0], alr[0], b0h);
                    mma_bf16(acc[1][n0], alr[1], b0h);
                    mma_bf16(acc[0][n1], alr[0], b1h);
                    mma_bf16(acc[1][n1], alr[1], b1h);
                }
            }
        }

        __syncthreads();
        if (kt + 2 < ntiles) issue(kt + 2, s);
    }

    const int cq = t << 1;
    #pragma unroll
    for (int ni = 0; ni < 8; ni++) {
        const int col = bn + warpN + (ni << 3) + cq;
        const float b0 = bias[col], b1 = bias[col + 1];
        #pragma unroll
        for (int mi = 0; mi < 2; mi++) {
            const int row0 = bm + warpM + (mi << 4) + g;
            float2 v0, v1;
            v0.x = acc[mi][ni][0] + b0; v0.y = acc[mi][ni][1] + b1;
            v1.x = acc[mi][ni][2] + b0; v1.y = acc[mi][ni][3] + b1;
            if (Radd) {
                float2 r0 = *(const float2*)&Radd[(size_t)row0 * N + col];
                float2 r1 = *(const float2*)&Radd[(size_t)(row0 + 8) * N + col];
                v0.x += r0.x; v0.y += r0.y;
                v1.x += r1.x; v1.y += r1.y;
            }
            if (relu) {
                v0.x = fmaxf(v0.x, 0.f); v0.y = fmaxf(v0.y, 0.f);
                v1.x = fmaxf(v1.x, 0.f); v1.y = fmaxf(v1.y, 0.f);
            }
            if (C) {
                *(float2*)&C[(size_t)row0 * N + col] = v0;
                *(float2*)&C[(size_t)(row0 + 8) * N + col] = v1;
            }
            if (Ch) {
                const int NP = N >> 1;
                const int pc = col >> 1;
                uint32_t ph, pl;
                split2(v0.x, v0.y, ph, pl);
                Ch[(size_t)row0 * NP + pc] = ph;
                Cl[(size_t)row0 * NP + pc] = pl;
                split2(v1.x, v1.y, ph, pl);
                Ch[(size_t)(row0 + 8) * NP + pc] = ph;
                Cl[(size_t)(row0 + 8) * NP + pc] = pl;
            }
        }
    }
}

// ---------------- bf16x3 MMA flash attention: register-resident P --------------
// 8 warps x 16 q-rows (128 q/CTA). QK score fragments are re-packed IN REGISTERS
// into PV A-fragments (same lane, same values as the old SMEM round-trip ->
// bit-identical). Removes P stores+loads (~20% of the measured 72% L1 bind).
// SMEM: KPh 0, KPl 2304, VPh 4608, VPl 6784 (u32) = 35840 B.
#define FLASH_SMEM_BYTES (8960 * 4)

__global__ void __launch_bounds__(256, 2) flash_mma_kernel(
    const uint32_t* __restrict__ qkvh, const uint32_t* __restrict__ qkvl,
    uint32_t* __restrict__ attnh, uint32_t* __restrict__ attnl)
{
    extern __shared__ uint32_t S[];
    uint32_t* KPh = S;            // [64][36]  key x d-pair
    uint32_t* KPl = S + 2304;
    uint32_t* VPh = S + 4608;     // [32][68]  k-pair x d
    uint32_t* VPl = S + 6784;

    const int tid  = threadIdx.x;
    const int lane = tid & 31;
    const int w    = tid >> 5;
    const int g    = lane >> 2;
    const int t    = lane & 3;
    const int qb   = blockIdx.x;
    const int bh   = blockIdx.y;
    const int b    = bh >> 2, h = bh & 3;

    const uint32_t sbase = (uint32_t)__cvta_generic_to_shared(S);
    const uint32_t* kph = qkvh + (size_t)b * 1024 * 384 + 128 + h * 32;
    const uint32_t* kpl = qkvl + (size_t)b * 1024 * 384 + 128 + h * 32;
    const uint32_t* vph = qkvh + (size_t)b * 1024 * 384 + 256 + h * 32;
    const uint32_t* vpl = qkvl + (size_t)b * 1024 * 384 + 256 + h * 32;

    const int wr = w * 16;
    const float SCALE = 0.125f;
    const float L2E   = 1.4426950408889634f;

    uint32_t qh[4][4], ql[4][4];
    {
        const size_t q0 = (size_t)(b * 1024 + qb * 128 + wr + g) * 384 + h * 32;
        const size_t q1 = q0 + (size_t)8 * 384;
        #pragma unroll
        for (int c = 0; c < 4; c++) {
            const int p = c * 8 + t;
            qh[c][0] = qkvh[q0 + p];     ql[c][0] = qkvl[q0 + p];
            qh[c][1] = qkvh[q1 + p];     ql[c][1] = qkvl[q1 + p];
            qh[c][2] = qkvh[q0 + p + 4]; ql[c][2] = qkvl[q0 + p + 4];
            qh[c][3] = qkvh[q1 + p + 4]; ql[c][3] = qkvl[q1 + p + 4];
        }
    }

    float oacc[8][4];
    #pragma unroll
    for (int nt = 0; nt < 8; nt++)
        #pragma unroll
        for (int r = 0; r < 4; r++) oacc[nt][r] = 0.f;
    float m0 = -1e30f, m1 = -1e30f, l0 = 0.f, l1 = 0.f;

    for (int kb = 0; kb < 16; kb++) {
        // ---- K tile: cp.async pre-split pairs ----
        #pragma unroll
        for (int i = 0; i < 2; i++) {
            const int idx = i * 256 + tid;
            const int row = idx >> 3, q4 = (idx & 7) << 2;
            const size_t go = (size_t)(kb * 64 + row) * 384 + q4;
            const uint32_t so = (uint32_t)(row * 36 + q4) * 4u;
            cp_async16(sbase + so, kph + go);
            cp_async16(sbase + 2304u * 4u + so, kpl + go);
        }
        asm volatile("cp.async.commit_group;\n");

        // ---- V tile: re-pair via PRMT ----
        {
            const int k2 = tid >> 3, j = tid & 7;
            const size_t r0 = (size_t)(kb * 64 + 2 * k2) * 384 + 4 * j;
            uint4 Ahv = *(const uint4*)&vph[r0];
            uint4 Bhv = *(const uint4*)&vph[r0 + 384];
            uint4 Alv = *(const uint4*)&vpl[r0];
            uint4 Blv = *(const uint4*)&vpl[r0 + 384];

            uint4 o0, o1;
            o0.x = prmt(Ahv.x, Bhv.x, 0x5410u); o0.y = prmt(Ahv.x, Bhv.x, 0x7632u);
            o0.z = prmt(Ahv.y, Bhv.y, 0x5410u); o0.w = prmt(Ahv.y, Bhv.y, 0x7632u);
            o1.x = prmt(Ahv.z, Bhv.z, 0x5410u); o1.y = prmt(Ahv.z, Bhv.z, 0x7632u);
            o1.z = prmt(Ahv.w, Bhv.w, 0x5410u); o1.w = prmt(Ahv.w, Bhv.w, 0x7632u);
            *(uint4*)&VPh[k2 * 68 + 8 * j]     = o0;
            *(uint4*)&VPh[k2 * 68 + 8 * j + 4] = o1;

            o0.x = prmt(Alv.x, Blv.x, 0x5410u); o0.y = prmt(Alv.x, Blv.x, 0x7632u);
            o0.z = prmt(Alv.y, Blv.y, 0x5410u); o0.w = prmt(Alv.y, Blv.y, 0x7632u);
            o1.x = prmt(Alv.z, Blv.z, 0x5410u); o1.y = prmt(Alv.z, Blv.z, 0x7632u);
            o1.z = prmt(Alv.w, Blv.w, 0x5410u); o1.w = prmt(Alv.w, Blv.w, 0x7632u);
            *(uint4*)&VPl[k2 * 68 + 8 * j]     = o0;
            *(uint4*)&VPl[k2 * 68 + 8 * j + 4] = o1;
        }
        asm volatile("cp.async.wait_group 0;\n" ::: "memory");
        __syncthreads();

        // ---- QK^T (bf16x3) ----
        float sc[8][4];
        #pragma unroll
        for (int nt = 0; nt < 8; nt++)
            #pragma unroll
            for (int r = 0; r < 4; r++) sc[nt][r] = 0.f;

        #pragma unroll
        for (int c = 0; c < 4; c++) {
            const int c8 = c * 8 + t;
            #pragma unroll
            for (int nt = 0; nt < 8; nt++) {
                const uint32_t* kr = &KPh[(nt * 8 + g) * 36];
                const uint32_t* kl = &KPl[(nt * 8 + g) * 36];
                uint32_t bh2[2] = { kr[c8], kr[c8 + 4] };
                uint32_t bl2[2] = { kl[c8], kl[c8 + 4] };
                mma_bf16(sc[nt], qh[c], bh2);
                mma_bf16(sc[nt], qh[c], bl2);
                mma_bf16(sc[nt], ql[c], bh2);
            }
        }

        // ---- online softmax ----
        float mb0 = -1e30f, mb1 = -1e30f;
        #pragma unroll
        for (int nt = 0; nt < 8; nt++) {
            sc[nt][0] *= SCALE; sc[nt][1] *= SCALE;
            sc[nt][2] *= SCALE; sc[nt][3] *= SCALE;
            mb0 = fmaxf(mb0, fmaxf(sc[nt][0], sc[nt][1]));
            mb1 = fmaxf(mb1, fmaxf(sc[nt][2], sc[nt][3]));
        }
        #pragma unroll
        for (int off = 1; off <= 2; off <<= 1) {
            mb0 = fmaxf(mb0, __shfl_xor_sync(0xffffffffu, mb0, off));
            mb1 = fmaxf(mb1, __shfl_xor_sync(0xffffffffu, mb1, off));
        }
        const float mn0 = fmaxf(m0, mb0);
        const float mn1 = fmaxf(m1, mb1);
        const float c0 = exp2f((m0 - mn0) * L2E);
        const float c1 = exp2f((m1 - mn1) * L2E);
        l0 *= c0; l1 *= c1;
        #pragma unroll
        for (int nt = 0; nt < 8; nt++) {
            oacc[nt][0] *= c0; oacc[nt][1] *= c0;
            oacc[nt][2] *= c1; oacc[nt][3] *= c1;
        }
        #pragma unroll
        for (int nt = 0; nt < 8; nt++) {
            sc[nt][0] = exp2f((sc[nt][0] - mn0) * L2E);
            sc[nt][1] = exp2f((sc[nt][1] - mn0) * L2E);
            sc[nt][2] = exp2f((sc[nt][2] - mn1) * L2E);
            sc[nt][3] = exp2f((sc[nt][3] - mn1) * L2E);
            l0 += sc[nt][0] + sc[nt][1];
            l1 += sc[nt][2] + sc[nt][3];
        }
        m0 = mn0; m1 = mn1;

        // ---- P @ V with register-resident P fragments ----
        // PV A-fragment for k-chunk c: a0=pack(sc[2c][0],[1]) (rows g, keys 16c+2t..+1),
        // a1=pack(sc[2c][2],[3]) (rows g+8), a2=pack(sc[2c+1][0],[1]) (keys +8),
        // a3=pack(sc[2c+1][2],[3]). Same lane/values as old SMEM round-trip.
        #pragma unroll
        for (int c = 0; c < 4; c++) {
            const int c8 = c * 8 + t;
            uint32_t ah2[4], al2[4];
            split2(sc[2 * c][0],     sc[2 * c][1],     ah2[0], al2[0]);
            split2(sc[2 * c][2],     sc[2 * c][3],     ah2[1], al2[1]);
            split2(sc[2 * c + 1][0], sc[2 * c + 1][1], ah2[2], al2[2]);
            split2(sc[2 * c + 1][2], sc[2 * c + 1][3], ah2[3], al2[3]);
            #pragma unroll
            for (int nt = 0; nt < 8; nt++) {
                const int vc = nt * 8 + g;
                uint32_t bh2[2] = { VPh[(c8) * 68 + vc], VPh[(c8 + 4) * 68 + vc] };
                uint32_t bl2[2] = { VPl[(c8) * 68 + vc], VPl[(c8 + 4) * 68 + vc] };
                mma_bf16(oacc[nt], ah2, bh2);
                mma_bf16(oacc[nt], ah2, bl2);
                mma_bf16(oacc[nt], al2, bh2);
            }
        }
        __syncthreads();   // K/V reads complete before next tile overwrites
    }

    #pragma unroll
    for (int off = 1; off <= 2; off <<= 1) {
        l0 += __shfl_xor_sync(0xffffffffu, l0, off);
        l1 += __shfl_xor_sync(0xffffffffu, l1, off);
    }
    const float inv0 = 1.f / l0;
    const float inv1 = 1.f / l1;

    const int row0 = b * 1024 + qb * 128 + wr + g;
    #pragma unroll
    for (int nt = 0; nt < 8; nt++) {
        const int pc = h * 32 + (nt << 2) + t;
        uint32_t ph, pl;
        split2(oacc[nt][0] * inv0, oacc[nt][1] * inv0, ph, pl);
        attnh[(size_t)row0 * 128 + pc] = ph;
        attnl[(size_t)row0 * 128 + pc] = pl;
        split2(oacc[nt][2] * inv1, oacc[nt][3] * inv1, ph, pl);
        attnh[(size_t)(row0 + 8) * 128 + pc] = ph;
        attnl[(size_t)(row0 + 8) * 128 + pc] = pl;
    }
}

// ---------------- layernorm (R14 verbatim) ----------------
__global__ void __launch_bounds__(256) ln_kernel(
    const float* __restrict__ xa,
    const float* __restrict__ g, const float* __restrict__ bt,
    float* __restrict__ out, uint32_t* __restrict__ oh, uint32_t* __restrict__ ol)
{
    const int warp = threadIdx.x >> 5, lane = threadIdx.x & 31;
    const size_t row = (size_t)blockIdx.x * 8 + warp;
    const float* pa = xa + row * 256 + lane * 8;

    float v[8];
    *(float4*)&v[0] = *(const float4*)pa;
    *(float4*)&v[4] = *(const float4*)(pa + 4);

    float s = ((v[0] + v[1]) + (v[2] + v[3])) + ((v[4] + v[5]) + (v[6] + v[7]));
    #pragma unroll
    for (int off = 16; off > 0; off >>= 1) s += __shfl_xor_sync(0xffffffffu, s, off);
    float mean = s * (1.f / 256.f);

    float vs = 0.f;
    #pragma unroll
    for (int i = 0; i < 8; i++) { float d = v[i] - mean; vs += d * d; }
    #pragma unroll
    for (int off = 16; off > 0; off >>= 1) vs += __shfl_xor_sync(0xffffffffu, vs, off);
    float inv = 1.f / sqrtf(vs * (1.f / 256.f) + 1e-5f);

    float gg[8], bb[8];
    *(float4*)&gg[0] = *(const float4*)(g + lane * 8);
    *(float4*)&gg[4] = *(const float4*)(g + lane * 8 + 4);
    *(float4*)&bb[0] = *(const float4*)(bt + lane * 8);
    *(float4*)&bb[4] = *(const float4*)(bt + lane * 8 + 4);

    float o[8];
    #pragma unroll
    for (int i = 0; i < 8; i++) o[i] = (v[i] - mean) * inv * gg[i] + bb[i];

    float* po = out + row * 256 + lane * 8;
    *(float4*)po = *(float4*)&o[0];
    *(float4*)(po + 4) = *(float4*)&o[4];

    if (oh) {
        uint32_t ph[4], pl[4];
        #pragma unroll
        for (int j = 0; j < 4; j++) split2(o[2 * j], o[2 * j + 1], ph[j], pl[j]);
        *(uint4*)&oh[row * 128 + lane * 4] = *(uint4*)ph;
        *(uint4*)&ol[row * 128 + lane * 4] = *(uint4*)pl;
    }
}

// -------------------------------- launch ---------------------------------------
extern "C" void kernel_launch(void* const* d_in, const int* in_sizes, int n_in,
                              void* d_out, int out_size)
{
    const float* x     = (const float*)d_in[0];
    const float* Win   = (const float*)d_in[1];
    const float* Wres  = (const float*)d_in[2];
    const float* Wread = (const float*)d_in[3];
    const float* bread = (const float*)d_in[4];
    const float* Wqkv  = (const float*)d_in[5];
    const float* bqkv  = (const float*)d_in[6];
    const float* Wo    = (const float*)d_in[7];
    const float* bo    = (const float*)d_in[8];
    const float* g1    = (const float*)d_in[9];
    const float* b1    = (const float*)d_in[10];
    const float* g2    = (const float*)d_in[11];
    const float* b2    = (const float*)d_in[12];
    const float* W1    = (const float*)d_in[13];
    const float* c1    = (const float*)d_in[14];
    const float* W2    = (const float*)d_in[15];
    const float* c2    = (const float*)d_in[16];
    float* out = (float*)d_out;

    float *h, *tmp;
    uint32_t *zh, *qh, *ql_, *hh, *hl, *ath, *atl, *ffh, *ffl;
    uint32_t *wrh, *wrl, *wqh, *wql, *woh, *wol, *w1h, *w1l, *w2h, *w2l;
    cudaGetSymbolAddress((void**)&h,   g_h);
    cudaGetSymbolAddress((void**)&tmp, g_tmp);
    cudaGetSymbolAddress((void**)&zh,  g_zh);
    cudaGetSymbolAddress((void**)&qh,  g_qkvh);
    cudaGetSymbolAddress((void**)&ql_, g_qkvl);
    cudaGetSymbolAddress((void**)&hh,  g_hh);
    cudaGetSymbolAddress((void**)&hl,  g_hl);
    cudaGetSymbolAddress((void**)&ath, g_attnh);
    cudaGetSymbolAddress((void**)&atl, g_attnl);
    cudaGetSymbolAddress((void**)&ffh, g_ffh);
    cudaGetSymbolAddress((void**)&ffl, g_ffl);
    cudaGetSymbolAddress((void**)&wrh, g_wrh);
    cudaGetSymbolAddress((void**)&wrl, g_wrl);
    cudaGetSymbolAddress((void**)&wqh, g_wqh);
    cudaGetSymbolAddress((void**)&wql, g_wql);
    cudaGetSymbolAddress((void**)&woh, g_woh);
    cudaGetSymbolAddress((void**)&wol, g_wol);
    cudaGetSymbolAddress((void**)&w1h, g_w1h);
    cudaGetSymbolAddress((void**)&w1l, g_w1l);
    cudaGetSymbolAddress((void**)&w2h, g_w2h);
    cudaGetSymbolAddress((void**)&w2l, g_w2l);

    cudaFuncSetAttribute(gemm_bf16x3,
                         cudaFuncAttributeMaxDynamicSharedMemorySize,
                         GEMM_SMEM_BYTES);
    cudaFuncSetAttribute(flash_mma_kernel,
                         cudaFuncAttributeMaxDynamicSharedMemorySize,
                         FLASH_SMEM_BYTES);

    const int M = 32768;
    const int SB = GEMM_SMEM_BYTES;

    prologue_kernel<<<148, 512>>>(x, Win, Wres, zh,
                                  Wread, Wqkv, Wo, W1, W2,
                                  wrh, wrl, wqh, wql, woh, wol,
                                  w1h, w1l, w2h, w2l);

    gemm_bf16x3<<<dim3(2, 256), 256, SB>>>(zh, nullptr, wrh, wrl, bread, nullptr,
                                           h, hh, hl, M, 256, 512, 0);

    for (int l = 0; l < 2; l++) {
        gemm_bf16x3<<<dim3(6, 256), 256, SB>>>(hh, hl,
            wqh + (size_t)l * 768 * 128, wql + (size_t)l * 768 * 128,
            bqkv + l * 768, nullptr, nullptr, qh, ql_, M, 768, 256, 0);
        flash_mma_kernel<<<dim3(8, 128), 256, FLASH_SMEM_BYTES>>>(qh, ql_, ath, atl);
        gemm_bf16x3<<<dim3(2, 256), 256, SB>>>(ath, atl,
            woh + (size_t)l * 256 * 128, wol + (size_t)l * 256 * 128,
            bo + l * 256, h, tmp, nullptr, nullptr, M, 256, 256, 0);
        ln_kernel<<<4096, 256>>>(tmp, g1 + l * 256, b1 + l * 256, h, hh, hl);
        gemm_bf16x3<<<dim3(8, 256), 256, SB>>>(hh, hl,
            w1h + (size_t)l * 1024 * 128, w1l + (size_t)l * 1024 * 128,
            c1 + l * 1024, nullptr, nullptr, ffh, ffl, M, 1024, 256, 1);
        gemm_bf16x3<<<dim3(2, 256), 256, SB>>>(ffh, ffl,
            w2h + (size_t)l * 256 * 512, w2l + (size_t)l * 256 * 512,
            c2 + l * 256, h, tmp, nullptr, nullptr, M, 256, 1024, 0);
        ln_kernel<<<4096, 256>>>(tmp, g2 + l * 256, b2 + l * 256,
                                 (l == 1) ? out : h,
                                 (l == 1) ? nullptr : hh,
                                 (l == 1) ? nullptr : hl);
    }
}